// round 3
// baseline (speedup 1.0000x reference)
#include <cuda_runtime.h>
#include <cuda_bf16.h>
#include <math.h>
#include <stdint.h>

// ---------------- problem constants ----------------
constexpr int B = 4, S = 1024, D = 512, M = 64, H = 8, WIN = 128;
constexpr int T = M + S;            // 1088
constexpr int BT = B * T;           // 4352
constexpr int HD = D / H;           // 64
constexpr float LR = 1e-3f, WD = 1e-2f, MAX_ALR = 0.1f, EPS = 1e-8f;
constexpr size_t BTD = (size_t)BT * D;
constexpr int SPLK = 8;             // split-K factor for TN grad GEMMs

// ---------------- scratch (static device globals; no allocation) ----------------
__device__ float g_xm[BTD];
__device__ float g_q[BTD];
__device__ float g_k[BTD];
__device__ float g_v[BTD];
__device__ float g_w[BT];
__device__ float g_z1[BTD];
__device__ float g_h1[BTD];
__device__ float g_z2[BTD];
__device__ float g_preds[BTD];
__device__ float g_g2[BTD];
__device__ float g_dz2[BTD];
__device__ float g_dh1[BTD];
__device__ float g_dz1[BTD];
__device__ float g_gW[2 * D * D];
__device__ float g_gb[2 * D];
__device__ float g_Wu[2 * D * D];
__device__ float g_bu[2 * D];
__device__ float g_r1[BTD];
__device__ float g_r[BTD];
__device__ float g_qkv[3 * BTD];
__device__ float g_o[BTD];
__device__ float g_part[SPLK * D * D];

// ---------------- tf32 / async helpers ----------------
__device__ __forceinline__ uint32_t f2tf32(float x) {
    uint32_t r;
    asm("cvt.rna.tf32.f32 %0, %1;" : "=r"(r) : "f"(x));
    return r;
}

__device__ __forceinline__ void split2(float f, uint32_t& hi, uint32_t& lo) {
    uint32_t h = f2tf32(f);
    float rem = f - __uint_as_float(h);
    hi = h;
    lo = f2tf32(rem);
}

__device__ __forceinline__ void mma_tf32(float* d, const uint32_t* a, const uint32_t* b) {
    asm volatile(
        "mma.sync.aligned.m16n8k8.row.col.f32.tf32.tf32.f32 "
        "{%0,%1,%2,%3}, {%4,%5,%6,%7}, {%8,%9}, {%0,%1,%2,%3};"
        : "+f"(d[0]), "+f"(d[1]), "+f"(d[2]), "+f"(d[3])
        : "r"(a[0]), "r"(a[1]), "r"(a[2]), "r"(a[3]), "r"(b[0]), "r"(b[1]));
}

__device__ __forceinline__ void cp_async16(void* smem_ptr, const void* gptr) {
    uint32_t sa = (uint32_t)__cvta_generic_to_shared(smem_ptr);
    asm volatile("cp.async.cg.shared.global [%0], [%1], 16;" :: "r"(sa), "l"(gptr));
}
__device__ __forceinline__ void cp_commit() { asm volatile("cp.async.commit_group;"); }
__device__ __forceinline__ void cp_wait0() { asm volatile("cp.async.wait_group 0;"); }
__device__ __forceinline__ void cp_wait1() { asm volatile("cp.async.wait_group 1;"); }

// swizzled [p][32] f32 layout (128B rows, 16B-group XOR swizzle)
__device__ __forceinline__ float lds_swz(const float* Sm, int p, int k) {
    return Sm[p * 32 + ((((k >> 2) ^ (p & 7)) << 2) | (k & 3))];
}

// ---------------- 3xTF32 MMA GEMM, cp.async double-buffered ----------------
// MODE: 0 = NN (A[M,K], B[K,N]); 1 = NT (A[M,K], B[N,K]); 2 = TN (A[K,M], B[K,N])
// EPI : 0 = C = AB + bias; 1 = C = AB; 2 = Z = AB + bias, C = R + silu(Z)
// ZMODE: 0 none; 1 split-K over blockIdx.z; 2 batched weights/outputs over blockIdx.z
#define GEMM_NN 0
#define GEMM_NT 1
#define GEMM_TN 2
#define EPI_BIAS 0
#define EPI_NONE 1
#define EPI_RESSILU 2

constexpr int BMt = 128, BNt = 128, BKt = 32;
constexpr int TILE_F = 32 * 136;               // 4352 floats per tile buffer (covers both layouts)
constexpr int SMEM_BYTES = 4 * TILE_F * 4;     // 2 matrices x 2 stages

template <int MODE, int EPI, int ZMODE, bool SLICED>
__global__ __launch_bounds__(256) void mma_gemm(
    const float* __restrict__ A, const float* __restrict__ Bm,
    const float* __restrict__ bias, const float* __restrict__ R,
    float* __restrict__ C, float* __restrict__ Zout,
    int Md, int Nd, int Kd) {
    extern __shared__ float smf[];
    float* As = smf;               // [2][TILE_F]
    float* Bs = smf + 2 * TILE_F;

    const int n0 = blockIdx.x * BNt;
    const int m0 = blockIdx.y * BMt;
    const int tid = threadIdx.x;
    const int warp = tid >> 5, lane = tid & 31;
    const int wm = warp >> 2, wn = warp & 3;    // 2 x 4 warp grid
    const int gid = lane >> 2, tig = lane & 3;

    if (ZMODE == 2) {
        Bm += (size_t)blockIdx.z * Kd * Nd;
        bias += (size_t)blockIdx.z * Nd;
        C += (size_t)blockIdx.z * Md * Nd;
    }

    // A row base (SLICED: compact output rows -> strided input rows, per-batch)
    const float* Arow;
    if (MODE == GEMM_TN) {
        Arow = A;  // use m0 as column offset
    } else if (SLICED) {
        int bb = m0 / S;
        Arow = A + ((size_t)(bb * T + M) + (m0 - bb * S)) * Kd;
    } else {
        Arow = A + (size_t)m0 * Kd;
    }

    int kbeg = 0, kend = Kd;
    if (ZMODE == 1) {
        int chunk = Kd / SPLK;
        kbeg = blockIdx.z * chunk;
        kend = kbeg + chunk;
    }
    const int nIter = (kend - kbeg) / BKt;

    float acc[4][4][4];
#pragma unroll
    for (int i = 0; i < 4; i++)
#pragma unroll
        for (int j = 0; j < 4; j++)
#pragma unroll
            for (int c = 0; c < 4; c++) acc[i][j][c] = 0.f;

    // ---- tile loaders (cp.async, 16B per op) ----
    auto loadA = [&](int k0, float* dst) {
        if (MODE == GEMM_TN) {
            int mg = tid & 31, kr = tid >> 5;
#pragma unroll
            for (int r = 0; r < 4; r++) {
                int k = kr + r * 8;
                cp_async16(dst + k * 136 + mg * 4, A + (size_t)(k0 + k) * Md + m0 + mg * 4);
            }
        } else {
            int kg = tid & 7, mr = tid >> 3;
#pragma unroll
            for (int r = 0; r < 4; r++) {
                int m = mr + r * 32;
                cp_async16(dst + m * 32 + ((kg ^ (m & 7)) << 2), Arow + (size_t)m * Kd + k0 + kg * 4);
            }
        }
    };
    auto loadB = [&](int k0, float* dst) {
        if (MODE == GEMM_NT) {
            int kg = tid & 7, nr = tid >> 3;
#pragma unroll
            for (int r = 0; r < 4; r++) {
                int n = nr + r * 32;
                cp_async16(dst + n * 32 + ((kg ^ (n & 7)) << 2), Bm + (size_t)(n0 + n) * Kd + k0 + kg * 4);
            }
        } else {
            int ng = tid & 31, kr = tid >> 5;
#pragma unroll
            for (int r = 0; r < 4; r++) {
                int k = kr + r * 8;
                cp_async16(dst + k * 136 + ng * 4, Bm + (size_t)(k0 + k) * Nd + n0 + ng * 4);
            }
        }
    };

    loadA(kbeg, As);
    loadB(kbeg, Bs);
    cp_commit();

    for (int it = 0; it < nIter; it++) {
        if (it + 1 < nIter) {
            float* an = As + ((it + 1) & 1) * TILE_F;
            float* bn = Bs + ((it + 1) & 1) * TILE_F;
            loadA(kbeg + (it + 1) * BKt, an);
            loadB(kbeg + (it + 1) * BKt, bn);
            cp_commit();
            cp_wait1();
        } else {
            cp_wait0();
        }
        __syncthreads();

        const float* a = As + (it & 1) * TILE_F;
        const float* b = Bs + (it & 1) * TILE_F;

#pragma unroll
        for (int kk = 0; kk < BKt; kk += 8) {
            uint32_t ah[4][4], al[4][4];
#pragma unroll
            for (int im = 0; im < 4; im++) {
                int mrow = wm * 64 + im * 16 + gid;
                float f0, f1, f2, f3;
                if (MODE == GEMM_TN) {
                    f0 = a[(kk + tig) * 136 + mrow];
                    f1 = a[(kk + tig) * 136 + mrow + 8];
                    f2 = a[(kk + tig + 4) * 136 + mrow];
                    f3 = a[(kk + tig + 4) * 136 + mrow + 8];
                } else {
                    f0 = lds_swz(a, mrow, kk + tig);
                    f1 = lds_swz(a, mrow + 8, kk + tig);
                    f2 = lds_swz(a, mrow, kk + tig + 4);
                    f3 = lds_swz(a, mrow + 8, kk + tig + 4);
                }
                split2(f0, ah[im][0], al[im][0]);
                split2(f1, ah[im][1], al[im][1]);
                split2(f2, ah[im][2], al[im][2]);
                split2(f3, ah[im][3], al[im][3]);
            }
#pragma unroll
            for (int jn = 0; jn < 4; jn++) {
                int ncol = wn * 32 + jn * 8 + gid;
                float g0, g1;
                if (MODE == GEMM_NT) {
                    g0 = lds_swz(b, ncol, kk + tig);
                    g1 = lds_swz(b, ncol, kk + tig + 4);
                } else {
                    g0 = b[(kk + tig) * 136 + ncol];
                    g1 = b[(kk + tig + 4) * 136 + ncol];
                }
                uint32_t bh[2], bl[2];
                split2(g0, bh[0], bl[0]);
                split2(g1, bh[1], bl[1]);
#pragma unroll
                for (int im = 0; im < 4; im++) {
                    mma_tf32(acc[im][jn], al[im], bh);
                    mma_tf32(acc[im][jn], ah[im], bl);
                    mma_tf32(acc[im][jn], ah[im], bh);
                }
            }
        }
        __syncthreads();
    }

    // ---- epilogue ----
    size_t Cbase = 0;
    if (ZMODE == 1) Cbase = (size_t)blockIdx.z * Md * Nd;
#pragma unroll
    for (int im = 0; im < 4; im++) {
#pragma unroll
        for (int jn = 0; jn < 4; jn++) {
            int lrow = wm * 64 + im * 16 + gid;
            int col = n0 + wn * 32 + jn * 8 + tig * 2;
#pragma unroll
            for (int rr = 0; rr < 2; rr++) {
                int r_ = m0 + lrow + rr * 8;
                float v0 = acc[im][jn][rr * 2 + 0];
                float v1 = acc[im][jn][rr * 2 + 1];
                if (EPI == EPI_BIAS || EPI == EPI_RESSILU) {
                    v0 += bias[col];
                    v1 += bias[col + 1];
                }
                size_t off = (size_t)r_ * Nd + col;
                if (EPI == EPI_RESSILU) {
                    if (Zout) { Zout[off] = v0; Zout[off + 1] = v1; }
                    float s0 = 1.f / (1.f + __expf(-v0));
                    float s1 = 1.f / (1.f + __expf(-v1));
                    v0 = R[off] + v0 * s0;
                    v1 = R[off + 1] + v1 * s1;
                }
                C[Cbase + off] = v0;
                C[Cbase + off + 1] = v1;
            }
        }
    }
}

// ---------------- split-K reduce ----------------
__global__ void reduce_part_kernel(const float* __restrict__ part, float* __restrict__ out, int n) {
    int i = blockIdx.x * 256 + threadIdx.x;
    if (i >= n) return;
    float s = 0.f;
#pragma unroll
    for (int z = 0; z < SPLK; z++) s += part[(size_t)z * n + i];
    out[i] = s;
}

// ---------------- elementwise / small kernels ----------------
__global__ void build_xm_kernel(const float* __restrict__ x, const float* __restrict__ meta,
                                float* __restrict__ xm) {
    size_t idx = (size_t)blockIdx.x * blockDim.x + threadIdx.x;
    if (idx >= BTD) return;
    int d = idx % D;
    int t = (idx / D) % T;
    int b = idx / ((size_t)D * T);
    xm[idx] = (t < M) ? meta[(size_t)t * D + d] : x[((size_t)b * S + (t - M)) * D + d];
}

__global__ void wlr_kernel(const float* __restrict__ xm, const float* __restrict__ Wlr,
                           const float* __restrict__ blr, float* __restrict__ w) {
    __shared__ float sm[256];
    int row = blockIdx.x;
    const float* xr = xm + (size_t)row * D;
    float s = 0.f;
    for (int d = threadIdx.x; d < D; d += 256) s += xr[d] * Wlr[d];
    sm[threadIdx.x] = s;
    __syncthreads();
    for (int st = 128; st > 0; st >>= 1) {
        if (threadIdx.x < st) sm[threadIdx.x] += sm[threadIdx.x + st];
        __syncthreads();
    }
    if (threadIdx.x == 0) {
        float z = sm[0] + blr[0];
        w[row] = (1.f / (1.f + __expf(-z))) * MAX_ALR;
    }
}

__device__ __forceinline__ float silu_grad(float z) {
    float sig = 1.f / (1.f + __expf(-z));
    return sig * (1.f + z * (1.f - sig));
}

__global__ void grad_out_kernel(const float* __restrict__ preds, const float* __restrict__ v,
                                const float* __restrict__ w, const float* __restrict__ z2,
                                float* __restrict__ g2, float* __restrict__ dz2) {
    size_t i = (size_t)blockIdx.x * blockDim.x + threadIdx.x;
    if (i >= BTD) return;
    int row = i / D;
    float g = w[row] * (2.0f / (float)D) * (preds[i] - v[i]);
    g2[i] = g;
    dz2[i] = g * silu_grad(z2[i]);
}

__global__ void dz1_kernel(const float* __restrict__ g2, const float* __restrict__ dh1,
                           const float* __restrict__ z1, float* __restrict__ dz1) {
    size_t i = (size_t)blockIdx.x * blockDim.x + threadIdx.x;
    if (i >= BTD) return;
    dz1[i] = (g2[i] + dh1[i]) * silu_grad(z1[i]);
}

__global__ void colsum_kernel(const float* __restrict__ X, float* __restrict__ out, int rows) {
    int c = threadIdx.x;  // blockDim = 512 = D
    int r0 = blockIdx.x * 64;
    int r1 = min(r0 + 64, rows);
    float s = 0.f;
    for (int r = r0; r < r1; r++) s += X[(size_t)r * D + c];
    atomicAdd(&out[c], s);
}

__global__ void adamw_kernel(const float* __restrict__ p, const float* __restrict__ g,
                             float* __restrict__ out, int n) {
    int i = blockIdx.x * blockDim.x + threadIdx.x;
    if (i >= n) return;
    float gv = g[i];
    out[i] = p[i] * (1.f - LR * WD) - LR * gv / (fabsf(gv) + EPS);
}

// ---------------- sliding window attention (8 queries / block, V staged in smem) ----------------
constexpr int QB = 8;
constexpr int KROWS = WIN + QB - 1;  // 135

__global__ __launch_bounds__(128) void attn_kernel2(
    const float* __restrict__ qkv, float* __restrict__ o) {
    __shared__ float Ksm[KROWS * 65];   // reused for V in second phase
    __shared__ float Qsm[QB * 64];
    __shared__ float sc[QB * 128];
    __shared__ float invs[QB];

    const float* qs = qkv;
    const float* ks = qkv + BTD;
    const float* vs = qkv + 2 * BTD;

    const int i0 = M + blockIdx.x * QB;
    const int h = blockIdx.y;
    const int b = blockIdx.z;
    const int tid = threadIdx.x;
    const int lane = tid & 31, w = tid >> 5;

    const int jlo = max(0, i0 - (WIN - 1));
    const int jhi = i0 + QB - 1;
    const int nrows = jhi - jlo + 1;  // <= 135

    for (int idx = tid; idx < nrows * 64; idx += 128) {
        int r = idx >> 6, d = idx & 63;
        Ksm[r * 65 + d] = ks[((size_t)(b * T + jlo + r)) * D + h * HD + d];
    }
    for (int idx = tid; idx < QB * 64; idx += 128) {
        Qsm[idx] = qs[((size_t)(b * T + i0 + (idx >> 6))) * D + h * HD + (idx & 63)];
    }
    __syncthreads();

#pragma unroll
    for (int q = 0; q < QB; q++) {
        int j = (i0 + q) - (WIN - 1) + tid;
        float s = -1e30f;
        if (j >= 0) {
            int r = j - jlo;
            const float* kp = &Ksm[r * 65];
            const float* qp = &Qsm[q * 64];
            float acc = 0.f;
#pragma unroll
            for (int d = 0; d < HD; d++) acc += qp[d] * kp[d];
            s = acc * 0.125f;
        }
        sc[q * 128 + tid] = s;
    }
    __syncthreads();

    for (int q = w; q < QB; q += 4) {
        float x0 = sc[q * 128 + lane];
        float x1 = sc[q * 128 + lane + 32];
        float x2 = sc[q * 128 + lane + 64];
        float x3 = sc[q * 128 + lane + 96];
        float mx = fmaxf(fmaxf(x0, x1), fmaxf(x2, x3));
#pragma unroll
        for (int off = 16; off > 0; off >>= 1) mx = fmaxf(mx, __shfl_xor_sync(0xffffffffu, mx, off));
        float e0 = __expf(x0 - mx), e1 = __expf(x1 - mx), e2 = __expf(x2 - mx), e3 = __expf(x3 - mx);
        sc[q * 128 + lane] = e0;
        sc[q * 128 + lane + 32] = e1;
        sc[q * 128 + lane + 64] = e2;
        sc[q * 128 + lane + 96] = e3;
        float sum = e0 + e1 + e2 + e3;
#pragma unroll
        for (int off = 16; off > 0; off >>= 1) sum += __shfl_xor_sync(0xffffffffu, sum, off);
        if (lane == 0) invs[q] = 1.f / sum;
    }
    __syncthreads();

    // stage V into smem (overwrite Ksm; K no longer needed)
    for (int idx = tid; idx < nrows * 64; idx += 128) {
        int r = idx >> 6, d = idx & 63;
        Ksm[r * 65 + d] = vs[((size_t)(b * T + jlo + r)) * D + h * HD + d];
    }
    __syncthreads();

    const int d = tid & 63, g = tid >> 6;
    float acc[4] = {0.f, 0.f, 0.f, 0.f};
    for (int r = 0; r < nrows; r++) {
        float vv = Ksm[r * 65 + d];
        int j = jlo + r;
#pragma unroll
        for (int qi = 0; qi < 4; qi++) {
            int q = g + qi * 2;
            int jj = j - (i0 + q) + (WIN - 1);
            if (jj >= 0 && jj < WIN) acc[qi] += sc[q * 128 + jj] * vv;
        }
    }
#pragma unroll
    for (int qi = 0; qi < 4; qi++) {
        int q = g + qi * 2;
        o[((size_t)(b * T + i0 + q)) * D + h * HD + d] = acc[qi] * invs[q];
    }
}

// ---------------- host-side launch ----------------
template <int MODE, int EPI, int ZMODE, bool SLICED>
static void launch_gemm(dim3 grid, const float* A, const float* Bm, const float* bias,
                        const float* R, float* C, float* Z, int Md, int Nd, int Kd) {
    cudaFuncSetAttribute(mma_gemm<MODE, EPI, ZMODE, SLICED>,
                         cudaFuncAttributeMaxDynamicSharedMemorySize, SMEM_BYTES);
    mma_gemm<MODE, EPI, ZMODE, SLICED><<<grid, 256, SMEM_BYTES>>>(A, Bm, bias, R, C, Z, Md, Nd, Kd);
}

template <typename Tsym>
static float* sym(Tsym& s) {
    void* p = nullptr;
    cudaGetSymbolAddress(&p, s);
    return (float*)p;
}

extern "C" void kernel_launch(void* const* d_in, const int* in_sizes, int n_in,
                              void* d_out, int out_size) {
    const float* x     = (const float*)d_in[0];
    const float* meta  = (const float*)d_in[1];
    const float* lmm_W = (const float*)d_in[2];
    const float* lmm_b = (const float*)d_in[3];
    const float* Wq    = (const float*)d_in[4];
    const float* bq    = (const float*)d_in[5];
    const float* Wk    = (const float*)d_in[6];
    const float* bk    = (const float*)d_in[7];
    const float* Wv    = (const float*)d_in[8];
    const float* bv    = (const float*)d_in[9];
    const float* W_lr  = (const float*)d_in[10];
    const float* b_lr  = (const float*)d_in[11];
    const float* swa_W = (const float*)d_in[12];
    const float* swa_b = (const float*)d_in[13];
    float* out = (float*)d_out;

    float *xm = sym(g_xm), *q = sym(g_q), *k = sym(g_k), *v = sym(g_v), *w = sym(g_w);
    float *z1 = sym(g_z1), *h1 = sym(g_h1), *z2 = sym(g_z2), *preds = sym(g_preds);
    float *g2 = sym(g_g2), *dz2 = sym(g_dz2), *dh1 = sym(g_dh1), *dz1 = sym(g_dz1);
    float *gW = sym(g_gW), *gb = sym(g_gb), *Wu = sym(g_Wu), *bu = sym(g_bu);
    float *r1 = sym(g_r1), *r = sym(g_r), *qkv = sym(g_qkv);
    float *o = sym(g_o), *part = sym(g_part);

    const int EW_BLK = 256;
    const int ew_grid = (int)((BTD + EW_BLK - 1) / EW_BLK);
    const dim3 gBT(D / BNt, BT / BMt);           // (4, 34)
    const dim3 gSWA(D / BNt, BT / BMt, 3);       // batched q/k/v SWA projections
    const dim3 gTN(D / BNt, D / BMt, SPLK);      // (4, 4, 8)
    const dim3 gOUT(D / BNt, (B * S) / BMt);     // (4, 32) sliced

    // 1) xm = [meta ; x]
    build_xm_kernel<<<ew_grid, EW_BLK>>>(x, meta, xm);

    // 2) projections
    launch_gemm<GEMM_NN, EPI_BIAS, 0, false>(gBT, xm, Wq, bq, nullptr, q, nullptr, BT, D, D);
    launch_gemm<GEMM_NN, EPI_BIAS, 0, false>(gBT, xm, Wk, bk, nullptr, k, nullptr, BT, D, D);
    launch_gemm<GEMM_NN, EPI_BIAS, 0, false>(gBT, xm, Wv, bv, nullptr, v, nullptr, BT, D, D);

    // 3) adaptive lr
    wlr_kernel<<<BT, 256>>>(xm, W_lr, b_lr, w);

    // 4) lmm forward on k (save z1, z2, h1, preds)
    launch_gemm<GEMM_NN, EPI_RESSILU, 0, false>(gBT, k, lmm_W, lmm_b, k, h1, z1, BT, D, D);
    launch_gemm<GEMM_NN, EPI_RESSILU, 0, false>(gBT, h1, lmm_W + D * D, lmm_b + D, h1, preds, z2, BT, D, D);

    // 5) backward
    grad_out_kernel<<<ew_grid, EW_BLK>>>(preds, v, w, z2, g2, dz2);
    cudaMemsetAsync(gb, 0, 2 * D * sizeof(float));
    launch_gemm<GEMM_TN, EPI_NONE, 1, false>(gTN, h1, dz2, nullptr, nullptr, part, nullptr, D, D, BT);
    reduce_part_kernel<<<(D * D + 255) / 256, 256>>>(part, gW + D * D, D * D);
    colsum_kernel<<<(BT + 63) / 64, D>>>(dz2, gb + D, BT);
    launch_gemm<GEMM_NT, EPI_NONE, 0, false>(gBT, dz2, lmm_W + D * D, nullptr, nullptr, dh1, nullptr, BT, D, D);
    dz1_kernel<<<ew_grid, EW_BLK>>>(g2, dh1, z1, dz1);
    launch_gemm<GEMM_TN, EPI_NONE, 1, false>(gTN, k, dz1, nullptr, nullptr, part, nullptr, D, D, BT);
    reduce_part_kernel<<<(D * D + 255) / 256, 256>>>(part, gW, D * D);
    colsum_kernel<<<(BT + 63) / 64, D>>>(dz1, gb, BT);

    // 6) AdamW-style update
    adamw_kernel<<<(2 * D * D + 255) / 256, 256>>>(lmm_W, gW, Wu, 2 * D * D);
    adamw_kernel<<<(2 * D + 255) / 256, 256>>>(lmm_b, gb, bu, 2 * D);

    // 7) retrieval with updated memory
    launch_gemm<GEMM_NN, EPI_RESSILU, 0, false>(gBT, q, Wu, bu, q, r1, nullptr, BT, D, D);
    launch_gemm<GEMM_NN, EPI_RESSILU, 0, false>(gBT, r1, Wu + D * D, bu + D, r1, r, nullptr, BT, D, D);

    // 8) SWA q/k/v projections in one batched launch (contiguous weights/outputs)
    launch_gemm<GEMM_NN, EPI_BIAS, 2, false>(gSWA, r, swa_W, swa_b, nullptr, qkv, nullptr, BT, D, D);

    // 9) attention
    {
        dim3 grid(S / QB, H, B);
        attn_kernel2<<<grid, 128>>>(qkv, o);
    }

    // 10) output projection, all batches in one sliced launch writing d_out directly
    launch_gemm<GEMM_NN, EPI_BIAS, 0, true>(gOUT, o, swa_W + 3 * D * D, swa_b + 3 * D, nullptr, out, nullptr, B * S, D, D);
}

// round 4
// speedup vs baseline: 1.2010x; 1.2010x over previous
#include <cuda_runtime.h>
#include <cuda_bf16.h>
#include <math.h>
#include <stdint.h>

// ---------------- problem constants ----------------
constexpr int B = 4, S = 1024, D = 512, M = 64, H = 8, WIN = 128;
constexpr int T = M + S;            // 1088
constexpr int BT = B * T;           // 4352
constexpr int BS_ = B * S;          // 4096
constexpr int HD = D / H;           // 64
constexpr float LR = 1e-3f, WD = 1e-2f, MAX_ALR = 0.1f, EPS = 1e-8f;
constexpr size_t BTD = (size_t)BT * D;
constexpr size_t BSD = (size_t)BS_ * D;
constexpr int DD = D * D;
constexpr int SPLK = 8;

typedef __nv_bfloat16 bf16;

// ---------------- scratch (static device globals; no allocation) ----------------
// f32
__device__ float g_xm[BTD];
__device__ float g_q[BTD];
__device__ float g_k[BTD];
__device__ float g_v[BTD];
__device__ float g_w[BT];
__device__ float g_z1[BTD];
__device__ float g_h1[BTD];
__device__ float g_z2[BTD];
__device__ float g_preds[BTD];
__device__ float g_g2[BTD];
__device__ float g_dz2[BTD];
__device__ float g_dh1[BTD];
__device__ float g_dz1[BTD];
__device__ float g_gW[2 * DD];
__device__ float g_gb[2 * D];
__device__ float g_Wu[2 * DD];
__device__ float g_bu[2 * D];
__device__ float g_r1[BTD];
__device__ float g_qkv[3 * BTD];
__device__ float g_part[SPLK * DD];
// bf16 hi/lo activations (row-major [rows][k])
__device__ bf16 g_xm_h[BTD], g_xm_l[BTD];
__device__ bf16 g_q_h[BTD], g_q_l[BTD];
__device__ bf16 g_k_h[BTD], g_k_l[BTD];
__device__ bf16 g_h1_h[BTD], g_h1_l[BTD];
__device__ bf16 g_dz2_h[BTD], g_dz2_l[BTD];
__device__ bf16 g_r1_h[BTD], g_r1_l[BTD];
__device__ bf16 g_r_h[BTD], g_r_l[BTD];
__device__ bf16 g_o_h[BSD], g_o_l[BSD];
// bf16 transposed activations [D][BT]
__device__ bf16 g_kT_h[BTD], g_kT_l[BTD];
__device__ bf16 g_h1T_h[BTD], g_h1T_l[BTD];
__device__ bf16 g_dz2T_h[BTD], g_dz2T_l[BTD];
__device__ bf16 g_dz1T_h[BTD], g_dz1T_l[BTD];
// bf16 weights: transposed [out][in] slots 0..8 = Wq,Wk,Wv,W1,W2,swa0..3
__device__ bf16 g_wT_h[9 * DD], g_wT_l[9 * DD];
__device__ bf16 g_w2o_h[DD], g_w2o_l[DD];       // W2 original orientation
__device__ bf16 g_wuT_h[2 * DD], g_wuT_l[2 * DD];

// ---------------- helpers ----------------
__device__ __forceinline__ void bsplit(float f, bf16& h, bf16& l) {
    h = __float2bfloat16(f);
    l = __float2bfloat16(f - __bfloat162float(h));
}

__device__ __forceinline__ void mma_bf16(float* d, const uint32_t* a, const uint32_t* b) {
    asm volatile(
        "mma.sync.aligned.m16n8k16.row.col.f32.bf16.bf16.f32 "
        "{%0,%1,%2,%3}, {%4,%5,%6,%7}, {%8,%9}, {%0,%1,%2,%3};"
        : "+f"(d[0]), "+f"(d[1]), "+f"(d[2]), "+f"(d[3])
        : "r"(a[0]), "r"(a[1]), "r"(a[2]), "r"(a[3]), "r"(b[0]), "r"(b[1]));
}

__device__ __forceinline__ void cp_async16(void* smem_ptr, const void* gptr) {
    uint32_t sa = (uint32_t)__cvta_generic_to_shared(smem_ptr);
    asm volatile("cp.async.cg.shared.global [%0], [%1], 16;" :: "r"(sa), "l"(gptr));
}
__device__ __forceinline__ void cp_commit() { asm volatile("cp.async.commit_group;"); }
__device__ __forceinline__ void cp_wait0() { asm volatile("cp.async.wait_group 0;"); }
__device__ __forceinline__ void cp_wait1() { asm volatile("cp.async.wait_group 1;"); }

// ---------------- bf16x3 GEMM ----------------
// Uniform layout: C[m,n] = sum_k A[m][k] * B[n][k], A/B pre-split bf16 hi/lo.
// EPI: 0 bias; 1 none; 2 res+silu.  ZMODE: 0 none; 1 split-K z; 2 batched weights z.
#define EPI_BIAS 0
#define EPI_NONE 1
#define EPI_RESSILU 2

constexpr int RP = 20;                       // padded row stride (u32): 16 data + 4 pad
constexpr int TILE_U = 128 * RP;             // u32 per half-tile
constexpr int STAGE_U = 4 * TILE_U;          // Ahi,Alo,Bhi,Blo
constexpr int GSMEM = 2 * STAGE_U * 4;       // 80 KB

template <int EPI, int ZMODE>
__global__ __launch_bounds__(256, 1) void gemm_bf16x3(
    const bf16* __restrict__ Ah, const bf16* __restrict__ Al,
    const bf16* __restrict__ Bh, const bf16* __restrict__ Bl,
    const float* __restrict__ bias, const float* __restrict__ R,
    float* __restrict__ Cf, bf16* __restrict__ Ch, bf16* __restrict__ Cl,
    float* __restrict__ Zf, int Md, int Nd, int Kd) {
    extern __shared__ uint32_t sm[];

    const int n0 = blockIdx.x * 128;
    const int m0 = blockIdx.y * 128;
    const int tid = threadIdx.x;
    const int warp = tid >> 5, lane = tid & 31;
    const int wm = warp >> 2, wn = warp & 3;
    const int gid = lane >> 2, tig = lane & 3;

    if (ZMODE == 2) {
        size_t wo = (size_t)blockIdx.z * Kd * Nd;
        Bh += wo; Bl += wo;
        bias += (size_t)blockIdx.z * Nd;
        Cf += (size_t)blockIdx.z * Md * Nd;
    }
    int kbeg = 0, kend = Kd;
    if (ZMODE == 1) {
        int chunk = Kd / SPLK;
        kbeg = blockIdx.z * chunk;
        kend = kbeg + chunk;
        Cf += (size_t)blockIdx.z * Md * Nd;
    }
    const int nIter = (kend - kbeg) / 32;

    float acc[4][4][4];
#pragma unroll
    for (int i = 0; i < 4; i++)
#pragma unroll
        for (int j = 0; j < 4; j++)
#pragma unroll
            for (int c = 0; c < 4; c++) acc[i][j][c] = 0.f;

    // loader: 2 chunks of 16B per thread per half (128 rows x 4 chunks = 512)
    auto loadStage = [&](int k0, uint32_t* st) {
#pragma unroll
        for (int i = 0; i < 2; i++) {
            int chunk = tid * 2 + i;
            int row = chunk >> 2, j = chunk & 3;
            uint32_t* d0 = st + row * RP + j * 4;
            const size_t ga = (size_t)(m0 + row) * Kd + k0 + j * 8;
            const size_t gb = (size_t)(n0 + row) * Kd + k0 + j * 8;
            cp_async16(d0, Ah + ga);
            cp_async16(d0 + TILE_U, Al + ga);
            cp_async16(d0 + 2 * TILE_U, Bh + gb);
            cp_async16(d0 + 3 * TILE_U, Bl + gb);
        }
    };

    loadStage(kbeg, sm);
    cp_commit();

    for (int it = 0; it < nIter; it++) {
        if (it + 1 < nIter) {
            loadStage(kbeg + (it + 1) * 32, sm + ((it + 1) & 1) * STAGE_U);
            cp_commit();
            cp_wait1();
        } else {
            cp_wait0();
        }
        __syncthreads();

        const uint32_t* pAh = sm + (it & 1) * STAGE_U;
        const uint32_t* pAl = pAh + TILE_U;
        const uint32_t* pBh = pAh + 2 * TILE_U;
        const uint32_t* pBl = pAh + 3 * TILE_U;

#pragma unroll
        for (int s = 0; s < 2; s++) {
            uint32_t ah[4][4], al[4][4];
#pragma unroll
            for (int im = 0; im < 4; im++) {
                int r = wm * 64 + im * 16 + gid;
                int b0 = r * RP + s * 8;
                int b1 = b0 + 8 * RP;
                ah[im][0] = pAh[b0 + tig];
                ah[im][1] = pAh[b1 + tig];
                ah[im][2] = pAh[b0 + tig + 4];
                ah[im][3] = pAh[b1 + tig + 4];
                al[im][0] = pAl[b0 + tig];
                al[im][1] = pAl[b1 + tig];
                al[im][2] = pAl[b0 + tig + 4];
                al[im][3] = pAl[b1 + tig + 4];
            }
            uint32_t bh[4][2], bl[4][2];
#pragma unroll
            for (int jn = 0; jn < 4; jn++) {
                int n = wn * 32 + jn * 8 + gid;
                int c0 = n * RP + s * 8;
                bh[jn][0] = pBh[c0 + tig];
                bh[jn][1] = pBh[c0 + tig + 4];
                bl[jn][0] = pBl[c0 + tig];
                bl[jn][1] = pBl[c0 + tig + 4];
            }
#pragma unroll
            for (int im = 0; im < 4; im++)
#pragma unroll
                for (int jn = 0; jn < 4; jn++) {
                    mma_bf16(acc[im][jn], ah[im], bh[jn]);
                    mma_bf16(acc[im][jn], ah[im], bl[jn]);
                    mma_bf16(acc[im][jn], al[im], bh[jn]);
                }
        }
        __syncthreads();
    }

    // ---- epilogue ----
#pragma unroll
    for (int im = 0; im < 4; im++) {
#pragma unroll
        for (int jn = 0; jn < 4; jn++) {
            int col = n0 + wn * 32 + jn * 8 + tig * 2;
#pragma unroll
            for (int rr = 0; rr < 2; rr++) {
                int r_ = m0 + wm * 64 + im * 16 + gid + rr * 8;
                float v0 = acc[im][jn][rr * 2 + 0];
                float v1 = acc[im][jn][rr * 2 + 1];
                if (EPI == EPI_BIAS || EPI == EPI_RESSILU) {
                    v0 += bias[col];
                    v1 += bias[col + 1];
                }
                size_t off = (size_t)r_ * Nd + col;
                if (EPI == EPI_RESSILU) {
                    if (Zf) { Zf[off] = v0; Zf[off + 1] = v1; }
                    float s0 = 1.f / (1.f + __expf(-v0));
                    float s1 = 1.f / (1.f + __expf(-v1));
                    v0 = R[off] + v0 * s0;
                    v1 = R[off + 1] + v1 * s1;
                }
                if (Cf) { Cf[off] = v0; Cf[off + 1] = v1; }
                if (Ch) {
                    bf16 h0, l0, h1, l1;
                    bsplit(v0, h0, l0);
                    bsplit(v1, h1, l1);
                    Ch[off] = h0; Ch[off + 1] = h1;
                    Cl[off] = l0; Cl[off + 1] = l1;
                }
            }
        }
    }
}

// ---------------- split-K reduce ----------------
__global__ void reduce_part_kernel(const float* __restrict__ part, float* __restrict__ out, int n) {
    int i = blockIdx.x * 256 + threadIdx.x;
    if (i >= n) return;
    float s = 0.f;
#pragma unroll
    for (int z = 0; z < SPLK; z++) s += part[(size_t)z * n + i];
    out[i] = s;
}

// ---------------- weight split (transposed + W2 original), z = 0..9 ----------------
__global__ void wsplitT_kernel(const float* __restrict__ Wq, const float* __restrict__ Wk,
                               const float* __restrict__ Wv, const float* __restrict__ W1,
                               const float* __restrict__ W2, const float* __restrict__ swa) {
    __shared__ float t[32][33];
    int z = blockIdx.z;
    const float* src = (z == 0) ? Wq : (z == 1) ? Wk : (z == 2) ? Wv : (z == 3) ? W1
                     : (z == 4 || z == 9) ? W2 : swa + (size_t)(z - 5) * DD;
    int c0 = blockIdx.x * 32, r0 = blockIdx.y * 32;
    int tx = threadIdx.x, ty = threadIdx.y;  // (32, 8)
#pragma unroll
    for (int kk = 0; kk < 4; kk++)
        t[ty + 8 * kk][tx] = src[(size_t)(r0 + ty + 8 * kk) * D + c0 + tx];
    __syncthreads();
    if (z < 9) {
        bf16* dh = g_wT_h + (size_t)z * DD;
        bf16* dl = g_wT_l + (size_t)z * DD;
#pragma unroll
        for (int kk = 0; kk < 4; kk++) {
            float v = t[tx][ty + 8 * kk];
            bf16 h, l;
            bsplit(v, h, l);
            size_t o = (size_t)(c0 + ty + 8 * kk) * D + r0 + tx;
            dh[o] = h; dl[o] = l;
        }
    } else {
#pragma unroll
        for (int kk = 0; kk < 4; kk++) {
            float v = t[ty + 8 * kk][tx];
            bf16 h, l;
            bsplit(v, h, l);
            size_t o = (size_t)(r0 + ty + 8 * kk) * D + c0 + tx;
            g_w2o_h[o] = h; g_w2o_l[o] = l;
        }
    }
}

// updated-weight transpose-split: src Wu [2][D][D] -> g_wuT hi/lo [2][D][D] transposed
__global__ void wuT_kernel(const float* __restrict__ Wu) {
    __shared__ float t[32][33];
    int z = blockIdx.z;
    const float* src = Wu + (size_t)z * DD;
    bf16* dh = g_wuT_h + (size_t)z * DD;
    bf16* dl = g_wuT_l + (size_t)z * DD;
    int c0 = blockIdx.x * 32, r0 = blockIdx.y * 32;
    int tx = threadIdx.x, ty = threadIdx.y;
#pragma unroll
    for (int kk = 0; kk < 4; kk++)
        t[ty + 8 * kk][tx] = src[(size_t)(r0 + ty + 8 * kk) * D + c0 + tx];
    __syncthreads();
#pragma unroll
    for (int kk = 0; kk < 4; kk++) {
        float v = t[tx][ty + 8 * kk];
        bf16 h, l;
        bsplit(v, h, l);
        size_t o = (size_t)(c0 + ty + 8 * kk) * D + r0 + tx;
        dh[o] = h; dl[o] = l;
    }
}

// activation transpose-split: src f32 [BT][D] -> dst bf16 hi/lo [D][BT]
__global__ void actT_kernel(const float* __restrict__ src, bf16* __restrict__ dh,
                            bf16* __restrict__ dl) {
    __shared__ float t[32][33];
    int c0 = blockIdx.x * 32;  // D dim
    int r0 = blockIdx.y * 32;  // BT dim
    int tx = threadIdx.x, ty = threadIdx.y;
#pragma unroll
    for (int kk = 0; kk < 4; kk++)
        t[ty + 8 * kk][tx] = src[(size_t)(r0 + ty + 8 * kk) * D + c0 + tx];
    __syncthreads();
#pragma unroll
    for (int kk = 0; kk < 4; kk++) {
        float v = t[tx][ty + 8 * kk];
        bf16 h, l;
        bsplit(v, h, l);
        size_t o = (size_t)(c0 + ty + 8 * kk) * BT + r0 + tx;
        dh[o] = h; dl[o] = l;
    }
}

// ---------------- elementwise / small kernels ----------------
__global__ void build_xm_kernel(const float* __restrict__ x, const float* __restrict__ meta) {
    size_t idx = (size_t)blockIdx.x * blockDim.x + threadIdx.x;
    if (idx >= BTD) return;
    int d = idx % D;
    int t = (idx / D) % T;
    int b = idx / ((size_t)D * T);
    float v = (t < M) ? meta[(size_t)t * D + d] : x[((size_t)b * S + (t - M)) * D + d];
    g_xm[idx] = v;
    bsplit(v, g_xm_h[idx], g_xm_l[idx]);
}

__global__ void wlr_kernel(const float* __restrict__ xm, const float* __restrict__ Wlr,
                           const float* __restrict__ blr, float* __restrict__ w) {
    // one warp per row
    int row = blockIdx.x * 8 + (threadIdx.x >> 5);
    int lane = threadIdx.x & 31;
    const float* xr = xm + (size_t)row * D;
    float s = 0.f;
    for (int d = lane; d < D; d += 32) s += xr[d] * Wlr[d];
#pragma unroll
    for (int off = 16; off > 0; off >>= 1) s += __shfl_xor_sync(0xffffffffu, s, off);
    if (lane == 0) {
        float z = s + blr[0];
        w[row] = (1.f / (1.f + __expf(-z))) * MAX_ALR;
    }
}

__device__ __forceinline__ float silu_grad(float z) {
    float sig = 1.f / (1.f + __expf(-z));
    return sig * (1.f + z * (1.f - sig));
}

__global__ void grad_out_kernel(const float* __restrict__ preds, const float* __restrict__ v,
                                const float* __restrict__ w, const float* __restrict__ z2) {
    size_t i = (size_t)blockIdx.x * blockDim.x + threadIdx.x;
    if (i >= BTD) return;
    int row = i / D;
    float g = w[row] * (2.0f / (float)D) * (preds[i] - v[i]);
    g_g2[i] = g;
    float d = g * silu_grad(z2[i]);
    g_dz2[i] = d;
    bsplit(d, g_dz2_h[i], g_dz2_l[i]);
}

__global__ void dz1_kernel(const float* __restrict__ g2, const float* __restrict__ dh1,
                           const float* __restrict__ z1) {
    size_t i = (size_t)blockIdx.x * blockDim.x + threadIdx.x;
    if (i >= BTD) return;
    g_dz1[i] = (g2[i] + dh1[i]) * silu_grad(z1[i]);
}

__global__ void colsum_kernel(const float* __restrict__ X, float* __restrict__ out, int rows) {
    int c = threadIdx.x;  // blockDim = 512 = D
    int r0 = blockIdx.x * 64;
    int r1 = min(r0 + 64, rows);
    float s = 0.f;
    for (int r = r0; r < r1; r++) s += X[(size_t)r * D + c];
    atomicAdd(&out[c], s);
}

__global__ void adamw_kernel(const float* __restrict__ p, const float* __restrict__ g,
                             float* __restrict__ out, int n) {
    int i = blockIdx.x * blockDim.x + threadIdx.x;
    if (i >= n) return;
    float gv = g[i];
    out[i] = p[i] * (1.f - LR * WD) - LR * gv / (fabsf(gv) + EPS);
}

// ---------------- sliding window attention (8 queries / block) ----------------
constexpr int QB = 8;
constexpr int KROWS = WIN + QB - 1;  // 135

__global__ __launch_bounds__(128) void attn_kernel2(const float* __restrict__ qkv) {
    __shared__ float Ksm[KROWS * 65];
    __shared__ float Qsm[QB * 64];
    __shared__ float sc[QB * 128];
    __shared__ float invs[QB];

    const float* qs = qkv;
    const float* ks = qkv + BTD;
    const float* vs = qkv + 2 * BTD;

    const int i0 = M + blockIdx.x * QB;
    const int h = blockIdx.y;
    const int b = blockIdx.z;
    const int tid = threadIdx.x;
    const int lane = tid & 31, w = tid >> 5;

    const int jlo = max(0, i0 - (WIN - 1));
    const int nrows = (i0 + QB - 1) - jlo + 1;

    for (int idx = tid; idx < nrows * 64; idx += 128) {
        int r = idx >> 6, d = idx & 63;
        Ksm[r * 65 + d] = ks[((size_t)(b * T + jlo + r)) * D + h * HD + d];
    }
    for (int idx = tid; idx < QB * 64; idx += 128)
        Qsm[idx] = qs[((size_t)(b * T + i0 + (idx >> 6))) * D + h * HD + (idx & 63)];
    __syncthreads();

#pragma unroll
    for (int q = 0; q < QB; q++) {
        int j = (i0 + q) - (WIN - 1) + tid;
        float s = -1e30f;
        if (j >= 0) {
            int r = j - jlo;
            const float* kp = &Ksm[r * 65];
            const float* qp = &Qsm[q * 64];
            float acc = 0.f;
#pragma unroll
            for (int d = 0; d < HD; d++) acc += qp[d] * kp[d];
            s = acc * 0.125f;
        }
        sc[q * 128 + tid] = s;
    }
    __syncthreads();

    for (int q = w; q < QB; q += 4) {
        float x0 = sc[q * 128 + lane];
        float x1 = sc[q * 128 + lane + 32];
        float x2 = sc[q * 128 + lane + 64];
        float x3 = sc[q * 128 + lane + 96];
        float mx = fmaxf(fmaxf(x0, x1), fmaxf(x2, x3));
#pragma unroll
        for (int off = 16; off > 0; off >>= 1) mx = fmaxf(mx, __shfl_xor_sync(0xffffffffu, mx, off));
        float e0 = __expf(x0 - mx), e1 = __expf(x1 - mx), e2 = __expf(x2 - mx), e3 = __expf(x3 - mx);
        sc[q * 128 + lane] = e0;
        sc[q * 128 + lane + 32] = e1;
        sc[q * 128 + lane + 64] = e2;
        sc[q * 128 + lane + 96] = e3;
        float sum = e0 + e1 + e2 + e3;
#pragma unroll
        for (int off = 16; off > 0; off >>= 1) sum += __shfl_xor_sync(0xffffffffu, sum, off);
        if (lane == 0) invs[q] = 1.f / sum;
    }
    __syncthreads();

    // stage V (reuse Ksm)
    for (int idx = tid; idx < nrows * 64; idx += 128) {
        int r = idx >> 6, d = idx & 63;
        Ksm[r * 65 + d] = vs[((size_t)(b * T + jlo + r)) * D + h * HD + d];
    }
    __syncthreads();

    const int d = tid & 63, g = tid >> 6;
    float acc[4] = {0.f, 0.f, 0.f, 0.f};
    for (int r = 0; r < nrows; r++) {
        float vv = Ksm[r * 65 + d];
        int j = jlo + r;
#pragma unroll
        for (int qi = 0; qi < 4; qi++) {
            int q = g + qi * 2;
            int jj = j - (i0 + q) + (WIN - 1);
            if (jj >= 0 && jj < WIN) acc[qi] += sc[q * 128 + jj] * vv;
        }
    }
#pragma unroll
    for (int qi = 0; qi < 4; qi++) {
        int q = g + qi * 2;
        float ov = acc[qi] * invs[q];
        size_t off = ((size_t)(b * S + (i0 - M) + q)) * D + h * HD + d;  // compact rows
        bsplit(ov, g_o_h[off], g_o_l[off]);
    }
}

// ---------------- host-side launch ----------------
template <int EPI, int ZMODE>
static void launch_gemm(dim3 grid, const bf16* Ah, const bf16* Al, const bf16* Bh,
                        const bf16* Bl, const float* bias, const float* R, float* Cf,
                        bf16* Ch, bf16* Cl, float* Zf, int Md, int Nd, int Kd) {
    cudaFuncSetAttribute(gemm_bf16x3<EPI, ZMODE>,
                         cudaFuncAttributeMaxDynamicSharedMemorySize, GSMEM);
    gemm_bf16x3<EPI, ZMODE><<<grid, 256, GSMEM>>>(Ah, Al, Bh, Bl, bias, R, Cf, Ch, Cl, Zf,
                                                  Md, Nd, Kd);
}

template <typename Tsym>
static void* symp(Tsym& s) {
    void* p = nullptr;
    cudaGetSymbolAddress(&p, s);
    return p;
}

extern "C" void kernel_launch(void* const* d_in, const int* in_sizes, int n_in,
                              void* d_out, int out_size) {
    const float* x     = (const float*)d_in[0];
    const float* meta  = (const float*)d_in[1];
    const float* lmm_W = (const float*)d_in[2];
    const float* lmm_b = (const float*)d_in[3];
    const float* Wq    = (const float*)d_in[4];
    const float* bq    = (const float*)d_in[5];
    const float* Wk    = (const float*)d_in[6];
    const float* bk    = (const float*)d_in[7];
    const float* Wv    = (const float*)d_in[8];
    const float* bv    = (const float*)d_in[9];
    const float* W_lr  = (const float*)d_in[10];
    const float* b_lr  = (const float*)d_in[11];
    const float* swa_W = (const float*)d_in[12];
    const float* swa_b = (const float*)d_in[13];
    float* out = (float*)d_out;

    float *xm = (float*)symp(g_xm), *q = (float*)symp(g_q), *k = (float*)symp(g_k);
    float *v = (float*)symp(g_v), *w = (float*)symp(g_w);
    float *z1 = (float*)symp(g_z1), *h1 = (float*)symp(g_h1), *z2 = (float*)symp(g_z2);
    float *preds = (float*)symp(g_preds), *g2 = (float*)symp(g_g2);
    float *dz2 = (float*)symp(g_dz2), *dh1 = (float*)symp(g_dh1), *dz1 = (float*)symp(g_dz1);
    float *gW = (float*)symp(g_gW), *gb = (float*)symp(g_gb);
    float *Wu = (float*)symp(g_Wu), *bu = (float*)symp(g_bu);
    float *r1 = (float*)symp(g_r1), *qkv = (float*)symp(g_qkv), *part = (float*)symp(g_part);
    bf16 *xm_h = (bf16*)symp(g_xm_h), *xm_l = (bf16*)symp(g_xm_l);
    bf16 *q_h = (bf16*)symp(g_q_h), *q_l = (bf16*)symp(g_q_l);
    bf16 *k_h = (bf16*)symp(g_k_h), *k_l = (bf16*)symp(g_k_l);
    bf16 *h1_h = (bf16*)symp(g_h1_h), *h1_l = (bf16*)symp(g_h1_l);
    bf16 *dz2_h = (bf16*)symp(g_dz2_h), *dz2_l = (bf16*)symp(g_dz2_l);
    bf16 *r1_h = (bf16*)symp(g_r1_h), *r1_l = (bf16*)symp(g_r1_l);
    bf16 *r_h = (bf16*)symp(g_r_h), *r_l = (bf16*)symp(g_r_l);
    bf16 *o_h = (bf16*)symp(g_o_h), *o_l = (bf16*)symp(g_o_l);
    bf16 *kT_h = (bf16*)symp(g_kT_h), *kT_l = (bf16*)symp(g_kT_l);
    bf16 *h1T_h = (bf16*)symp(g_h1T_h), *h1T_l = (bf16*)symp(g_h1T_l);
    bf16 *dz2T_h = (bf16*)symp(g_dz2T_h), *dz2T_l = (bf16*)symp(g_dz2T_l);
    bf16 *dz1T_h = (bf16*)symp(g_dz1T_h), *dz1T_l = (bf16*)symp(g_dz1T_l);
    bf16 *wT_h = (bf16*)symp(g_wT_h), *wT_l = (bf16*)symp(g_wT_l);
    bf16 *w2o_h = (bf16*)symp(g_w2o_h), *w2o_l = (bf16*)symp(g_w2o_l);
    bf16 *wuT_h = (bf16*)symp(g_wuT_h), *wuT_l = (bf16*)symp(g_wuT_l);

    const int EW_BLK = 256;
    const int ew_grid = (int)((BTD + EW_BLK - 1) / EW_BLK);
    const dim3 gBT(D / 128, BT / 128);          // (4, 34)
    const dim3 gSWA(D / 128, BT / 128, 3);
    const dim3 gTN(D / 128, D / 128, SPLK);     // (4, 4, 8)
    const dim3 gOUT(D / 128, BS_ / 128);        // (4, 32)
    const dim3 tBlk(32, 8);
    const dim3 gActT(D / 32, BT / 32);          // (16, 136)

    // 0) weight splits (transposed; z=9 -> W2 original)
    wsplitT_kernel<<<dim3(16, 16, 10), tBlk>>>(Wq, Wk, Wv, lmm_W, lmm_W + DD, swa_W);

    // 1) xm = [meta ; x] (f32 + bf16)
    build_xm_kernel<<<ew_grid, EW_BLK>>>(x, meta);

    // 2) projections (q,k need bf16; v f32 only)
    launch_gemm<EPI_BIAS, 0>(gBT, xm_h, xm_l, wT_h + 0 * DD, wT_l + 0 * DD, bq, nullptr,
                             q, q_h, q_l, nullptr, BT, D, D);
    launch_gemm<EPI_BIAS, 0>(gBT, xm_h, xm_l, wT_h + 1 * DD, wT_l + 1 * DD, bk, nullptr,
                             k, k_h, k_l, nullptr, BT, D, D);
    launch_gemm<EPI_BIAS, 0>(gBT, xm_h, xm_l, wT_h + 2 * DD, wT_l + 2 * DD, bv, nullptr,
                             v, nullptr, nullptr, nullptr, BT, D, D);

    // 3) adaptive lr
    wlr_kernel<<<BT / 8, 256>>>(xm, W_lr, b_lr, w);

    // 4) lmm forward on k
    launch_gemm<EPI_RESSILU, 0>(gBT, k_h, k_l, wT_h + 3 * DD, wT_l + 3 * DD, lmm_b, k,
                                h1, h1_h, h1_l, z1, BT, D, D);
    launch_gemm<EPI_RESSILU, 0>(gBT, h1_h, h1_l, wT_h + 4 * DD, wT_l + 4 * DD, lmm_b + D, h1,
                                preds, nullptr, nullptr, z2, BT, D, D);

    // 5) backward
    grad_out_kernel<<<ew_grid, EW_BLK>>>(preds, v, w, z2);
    cudaMemsetAsync(gb, 0, 2 * D * sizeof(float));
    // transposed bf16 activations for grad GEMMs
    actT_kernel<<<gActT, tBlk>>>(k, kT_h, kT_l);
    actT_kernel<<<gActT, tBlk>>>(h1, h1T_h, h1T_l);
    actT_kernel<<<gActT, tBlk>>>(dz2, dz2T_h, dz2T_l);
    // gW2 = h1^T dz2  (A = h1T [D][BT], B = dz2T [D][BT]), split-K
    launch_gemm<EPI_NONE, 1>(gTN, h1T_h, h1T_l, dz2T_h, dz2T_l, nullptr, nullptr,
                             part, nullptr, nullptr, nullptr, D, D, BT);
    reduce_part_kernel<<<(DD + 255) / 256, 256>>>(part, gW + DD, DD);
    colsum_kernel<<<(BT + 63) / 64, D>>>(dz2, gb + D, BT);
    // dh1 = dz2 @ W2^T  (B = W2 original [i][o])
    launch_gemm<EPI_NONE, 0>(gBT, dz2_h, dz2_l, w2o_h, w2o_l, nullptr, nullptr,
                             dh1, nullptr, nullptr, nullptr, BT, D, D);
    dz1_kernel<<<ew_grid, EW_BLK>>>(g2, dh1, z1);
    actT_kernel<<<gActT, tBlk>>>(dz1, dz1T_h, dz1T_l);
    // gW1 = k^T dz1
    launch_gemm<EPI_NONE, 1>(gTN, kT_h, kT_l, dz1T_h, dz1T_l, nullptr, nullptr,
                             part, nullptr, nullptr, nullptr, D, D, BT);
    reduce_part_kernel<<<(DD + 255) / 256, 256>>>(part, gW, DD);
    colsum_kernel<<<(BT + 63) / 64, D>>>(dz1, gb, BT);

    // 6) AdamW-style update + transpose-split of updated weights
    adamw_kernel<<<(2 * DD + 255) / 256, 256>>>(lmm_W, gW, Wu, 2 * DD);
    adamw_kernel<<<(2 * D + 255) / 256, 256>>>(lmm_b, gb, bu, 2 * D);
    wuT_kernel<<<dim3(16, 16, 2), tBlk>>>(Wu);

    // 7) retrieval with updated memory
    launch_gemm<EPI_RESSILU, 0>(gBT, q_h, q_l, wuT_h, wuT_l, bu, q,
                                r1, r1_h, r1_l, nullptr, BT, D, D);
    launch_gemm<EPI_RESSILU, 0>(gBT, r1_h, r1_l, wuT_h + DD, wuT_l + DD, bu + D, r1,
                                nullptr, r_h, r_l, nullptr, BT, D, D);

    // 8) SWA q/k/v projections (batched over z)
    launch_gemm<EPI_BIAS, 2>(gSWA, r_h, r_l, wT_h + 5 * DD, wT_l + 5 * DD, swa_b, nullptr,
                             qkv, nullptr, nullptr, nullptr, BT, D, D);

    // 9) attention -> compact bf16 o [B*S][D]
    {
        dim3 grid(S / QB, H, B);
        attn_kernel2<<<grid, 128>>>(qkv);
    }

    // 10) output projection -> d_out
    launch_gemm<EPI_BIAS, 0>(gOUT, o_h, o_l, wT_h + 8 * DD, wT_l + 8 * DD, swa_b + 3 * D,
                             nullptr, out, nullptr, nullptr, nullptr, BS_, D, D);
}

// round 6
// speedup vs baseline: 1.3031x; 1.0850x over previous
#include <cuda_runtime.h>
#include <cuda_bf16.h>
#include <math.h>
#include <stdint.h>

// ---------------- problem constants ----------------
constexpr int B = 4, S = 1024, D = 512, M = 64, H = 8, WIN = 128;
constexpr int T = M + S;            // 1088
constexpr int BT = B * T;           // 4352
constexpr int BS_ = B * S;          // 4096
constexpr int HD = D / H;           // 64
constexpr float LR = 1e-3f, WD = 1e-2f, MAX_ALR = 0.1f, EPS = 1e-8f;
constexpr size_t BTD = (size_t)BT * D;
constexpr size_t BSD = (size_t)BS_ * D;
constexpr int DD = D * D;
constexpr int SPLK = 8;             // 4352/8 = 544 = 17*32

typedef __nv_bfloat16 bf16;

// ---------------- scratch (static device globals; no allocation) ----------------
__device__ float g_xm[BTD];
__device__ float g_q[BTD];
__device__ float g_k[BTD];
__device__ float g_v[BTD];
__device__ float g_w[BT];
__device__ float g_z1[BTD];
__device__ float g_h1[BTD];
__device__ float g_z2[BTD];
__device__ float g_preds[BTD];
__device__ float g_g2[BTD];
__device__ float g_dz2[BTD];
__device__ float g_dh1[BTD];
__device__ float g_dz1[BTD];
__device__ float g_gW[2 * DD];
__device__ float g_gb[2 * D];
__device__ float g_Wu[2 * DD];
__device__ float g_bu[2 * D];
__device__ float g_r1[BTD];
__device__ float g_qkv[3 * BTD];
__device__ float g_part[SPLK * DD];
// bf16 hi/lo activations (row-major [rows][k])
__device__ bf16 g_xm_h[BTD], g_xm_l[BTD];
__device__ bf16 g_q_h[BTD], g_q_l[BTD];
__device__ bf16 g_k_h[BTD], g_k_l[BTD];
__device__ bf16 g_h1_h[BTD], g_h1_l[BTD];
__device__ bf16 g_dz2_h[BTD], g_dz2_l[BTD];
__device__ bf16 g_r1_h[BTD], g_r1_l[BTD];
__device__ bf16 g_r_h[BTD], g_r_l[BTD];
__device__ bf16 g_o_h[BSD], g_o_l[BSD];
// bf16 transposed activations [D][BT]
__device__ bf16 g_kT_h[BTD], g_kT_l[BTD];
__device__ bf16 g_h1T_h[BTD], g_h1T_l[BTD];
__device__ bf16 g_dz2T_h[BTD], g_dz2T_l[BTD];
__device__ bf16 g_dz1T_h[BTD], g_dz1T_l[BTD];
// bf16 weights: transposed [out][in] slots 0..8 = Wq,Wk,Wv,W1,W2,swa0..3
__device__ bf16 g_wT_h[9 * DD], g_wT_l[9 * DD];
__device__ bf16 g_w2o_h[DD], g_w2o_l[DD];
__device__ bf16 g_wuT_h[2 * DD], g_wuT_l[2 * DD];

// ---------------- helpers ----------------
__device__ __forceinline__ void bsplit(float f, bf16& h, bf16& l) {
    h = __float2bfloat16(f);
    l = __float2bfloat16(f - __bfloat162float(h));
}

__device__ __forceinline__ void mma_bf16(float* d, const uint32_t* a, const uint32_t* b) {
    asm volatile(
        "mma.sync.aligned.m16n8k16.row.col.f32.bf16.bf16.f32 "
        "{%0,%1,%2,%3}, {%4,%5,%6,%7}, {%8,%9}, {%0,%1,%2,%3};"
        : "+f"(d[0]), "+f"(d[1]), "+f"(d[2]), "+f"(d[3])
        : "r"(a[0]), "r"(a[1]), "r"(a[2]), "r"(a[3]), "r"(b[0]), "r"(b[1]));
}

__device__ __forceinline__ void cp_async16(void* smem_ptr, const void* gptr) {
    uint32_t sa = (uint32_t)__cvta_generic_to_shared(smem_ptr);
    asm volatile("cp.async.cg.shared.global [%0], [%1], 16;" :: "r"(sa), "l"(gptr));
}
__device__ __forceinline__ void cp_commit() { asm volatile("cp.async.commit_group;"); }
template <int N>
__device__ __forceinline__ void cp_wait() { asm volatile("cp.async.wait_group %0;" :: "n"(N)); }

// ---------------- bf16x3 GEMM, 512 threads, 3-stage cp.async pipeline ----------------
// C[m,n] = sum_k A[m][k]*B[n][k], A/B pre-split bf16 hi/lo, 128x128 tile, BK=32.
#define EPI_BIAS 0
#define EPI_NONE 1
#define EPI_RESSILU 2

constexpr int RP = 20;                        // padded row stride (u32): 16 data + 4 pad
constexpr int TILE_U = 128 * RP;              // 2560 u32 per half-tile
constexpr int STAGE_U = 4 * TILE_U;           // Ahi,Alo,Bhi,Blo
constexpr int NSTG = 3;
constexpr int GSMEM = NSTG * STAGE_U * 4;     // 122880 B

template <int EPI, int ZMODE>  // ZMODE: 0 none; 1 split-K z; 2 batched weights z
__global__ __launch_bounds__(512, 1) void gemm_bf16x3(
    const bf16* __restrict__ Ah, const bf16* __restrict__ Al,
    const bf16* __restrict__ Bh, const bf16* __restrict__ Bl,
    const float* __restrict__ bias, const float* __restrict__ R,
    float* __restrict__ Cf, bf16* __restrict__ Ch, bf16* __restrict__ Cl,
    float* __restrict__ Zf, int Md, int Nd, int Kd) {
    extern __shared__ uint32_t sm[];

    const int n0 = blockIdx.x * 128;
    const int m0 = blockIdx.y * 128;
    const int tid = threadIdx.x;
    const int warp = tid >> 5, lane = tid & 31;
    const int wm = warp >> 2, wn = warp & 3;    // 4 x 4 warp grid, 32x32 warp tile
    const int gid = lane >> 2, tig = lane & 3;

    if (ZMODE == 2) {
        size_t wo = (size_t)blockIdx.z * Kd * Nd;
        Bh += wo; Bl += wo;
        bias += (size_t)blockIdx.z * Nd;
        Cf += (size_t)blockIdx.z * Md * Nd;
    }
    int kbeg = 0, kend = Kd;
    if (ZMODE == 1) {
        int chunk = Kd / SPLK;
        kbeg = blockIdx.z * chunk;
        kend = kbeg + chunk;
        Cf += (size_t)blockIdx.z * Md * Nd;
    }
    const int nIter = (kend - kbeg) / 32;

    float acc[2][4][4];
#pragma unroll
    for (int i = 0; i < 2; i++)
#pragma unroll
        for (int j = 0; j < 4; j++)
#pragma unroll
            for (int c = 0; c < 4; c++) acc[i][j][c] = 0.f;

    // loader: 512 threads, 1 16B chunk per half-tile per thread
    const int lrow = tid >> 2, lj = tid & 3;
    auto loadStage = [&](int k0, uint32_t* st) {
        uint32_t* d0 = st + lrow * RP + lj * 4;
        const size_t ga = (size_t)(m0 + lrow) * Kd + k0 + lj * 8;
        const size_t gb = (size_t)(n0 + lrow) * Kd + k0 + lj * 8;
        cp_async16(d0, Ah + ga);
        cp_async16(d0 + TILE_U, Al + ga);
        cp_async16(d0 + 2 * TILE_U, Bh + gb);
        cp_async16(d0 + 3 * TILE_U, Bl + gb);
        cp_commit();
    };

    loadStage(kbeg, sm);
    loadStage(kbeg + 32, sm + STAGE_U);
    loadStage(kbeg + 64, sm + 2 * STAGE_U);

    for (int it = 0; it < nIter; it++) {
        int rem = nIter - 1 - it;
        if (rem >= 2) cp_wait<2>();
        else if (rem == 1) cp_wait<1>();
        else cp_wait<0>();
        __syncthreads();

        const uint32_t* pAh = sm + (it % NSTG) * STAGE_U;
        const uint32_t* pAl = pAh + TILE_U;
        const uint32_t* pBh = pAh + 2 * TILE_U;
        const uint32_t* pBl = pAh + 3 * TILE_U;

#pragma unroll
        for (int s = 0; s < 2; s++) {
            uint32_t ah[2][4], al[2][4];
#pragma unroll
            for (int im = 0; im < 2; im++) {
                int r = wm * 32 + im * 16 + gid;
                int b0 = r * RP + s * 8;
                int b1 = b0 + 8 * RP;
                ah[im][0] = pAh[b0 + tig];
                ah[im][1] = pAh[b1 + tig];
                ah[im][2] = pAh[b0 + tig + 4];
                ah[im][3] = pAh[b1 + tig + 4];
                al[im][0] = pAl[b0 + tig];
                al[im][1] = pAl[b1 + tig];
                al[im][2] = pAl[b0 + tig + 4];
                al[im][3] = pAl[b1 + tig + 4];
            }
            uint32_t bh[4][2], bl[4][2];
#pragma unroll
            for (int jn = 0; jn < 4; jn++) {
                int n = wn * 32 + jn * 8 + gid;
                int c0 = n * RP + s * 8;
                bh[jn][0] = pBh[c0 + tig];
                bh[jn][1] = pBh[c0 + tig + 4];
                bl[jn][0] = pBl[c0 + tig];
                bl[jn][1] = pBl[c0 + tig + 4];
            }
#pragma unroll
            for (int im = 0; im < 2; im++)
#pragma unroll
                for (int jn = 0; jn < 4; jn++) {
                    mma_bf16(acc[im][jn], ah[im], bh[jn]);
                    mma_bf16(acc[im][jn], ah[im], bl[jn]);
                    mma_bf16(acc[im][jn], al[im], bh[jn]);
                }
        }
        __syncthreads();

        if (it + NSTG < nIter)
            loadStage(kbeg + (it + NSTG) * 32, sm + ((it + NSTG) % NSTG) * STAGE_U);
    }

    // ---- epilogue ----
#pragma unroll
    for (int im = 0; im < 2; im++) {
#pragma unroll
        for (int jn = 0; jn < 4; jn++) {
            int col = n0 + wn * 32 + jn * 8 + tig * 2;
#pragma unroll
            for (int rr = 0; rr < 2; rr++) {
                int r_ = m0 + wm * 32 + im * 16 + gid + rr * 8;
                float v0 = acc[im][jn][rr * 2 + 0];
                float v1 = acc[im][jn][rr * 2 + 1];
                if (EPI == EPI_BIAS || EPI == EPI_RESSILU) {
                    v0 += bias[col];
                    v1 += bias[col + 1];
                }
                size_t off = (size_t)r_ * Nd + col;
                if (EPI == EPI_RESSILU) {
                    if (Zf) { Zf[off] = v0; Zf[off + 1] = v1; }
                    float s0 = 1.f / (1.f + __expf(-v0));
                    float s1 = 1.f / (1.f + __expf(-v1));
                    v0 = R[off] + v0 * s0;
                    v1 = R[off + 1] + v1 * s1;
                }
                if (Cf) { Cf[off] = v0; Cf[off + 1] = v1; }
                if (Ch) {
                    bf16 h0, l0, h1, l1;
                    bsplit(v0, h0, l0);
                    bsplit(v1, h1, l1);
                    Ch[off] = h0; Ch[off + 1] = h1;
                    Cl[off] = l0; Cl[off + 1] = l1;
                }
            }
        }
    }
}

// ---------------- split-K reduce ----------------
__global__ void reduce_part_kernel(const float* __restrict__ part, float* __restrict__ out, int n) {
    int i = blockIdx.x * 256 + threadIdx.x;
    if (i >= n) return;
    float s = 0.f;
#pragma unroll
    for (int z = 0; z < SPLK; z++) s += part[(size_t)z * n + i];
    out[i] = s;
}

// ---------------- weight split (transposed + W2 original), z = 0..9 ----------------
__global__ void wsplitT_kernel(const float* __restrict__ Wq, const float* __restrict__ Wk,
                               const float* __restrict__ Wv, const float* __restrict__ W1,
                               const float* __restrict__ W2, const float* __restrict__ swa) {
    __shared__ float t[32][33];
    int z = blockIdx.z;
    const float* src = (z == 0) ? Wq : (z == 1) ? Wk : (z == 2) ? Wv : (z == 3) ? W1
                     : (z == 4 || z == 9) ? W2 : swa + (size_t)(z - 5) * DD;
    int c0 = blockIdx.x * 32, r0 = blockIdx.y * 32;
    int tx = threadIdx.x, ty = threadIdx.y;  // (32, 8)
#pragma unroll
    for (int kk = 0; kk < 4; kk++)
        t[ty + 8 * kk][tx] = src[(size_t)(r0 + ty + 8 * kk) * D + c0 + tx];
    __syncthreads();
    if (z < 9) {
        bf16* dh = g_wT_h + (size_t)z * DD;
        bf16* dl = g_wT_l + (size_t)z * DD;
#pragma unroll
        for (int kk = 0; kk < 4; kk++) {
            float v = t[tx][ty + 8 * kk];
            bf16 h, l;
            bsplit(v, h, l);
            size_t o = (size_t)(c0 + ty + 8 * kk) * D + r0 + tx;
            dh[o] = h; dl[o] = l;
        }
    } else {
#pragma unroll
        for (int kk = 0; kk < 4; kk++) {
            float v = t[ty + 8 * kk][tx];
            bf16 h, l;
            bsplit(v, h, l);
            size_t o = (size_t)(r0 + ty + 8 * kk) * D + c0 + tx;
            g_w2o_h[o] = h; g_w2o_l[o] = l;
        }
    }
}

__global__ void wuT_kernel(const float* __restrict__ Wu) {
    __shared__ float t[32][33];
    int z = blockIdx.z;
    const float* src = Wu + (size_t)z * DD;
    bf16* dh = g_wuT_h + (size_t)z * DD;
    bf16* dl = g_wuT_l + (size_t)z * DD;
    int c0 = blockIdx.x * 32, r0 = blockIdx.y * 32;
    int tx = threadIdx.x, ty = threadIdx.y;
#pragma unroll
    for (int kk = 0; kk < 4; kk++)
        t[ty + 8 * kk][tx] = src[(size_t)(r0 + ty + 8 * kk) * D + c0 + tx];
    __syncthreads();
#pragma unroll
    for (int kk = 0; kk < 4; kk++) {
        float v = t[tx][ty + 8 * kk];
        bf16 h, l;
        bsplit(v, h, l);
        size_t o = (size_t)(c0 + ty + 8 * kk) * D + r0 + tx;
        dh[o] = h; dl[o] = l;
    }
}

// activation transpose-split: src f32 [BT][D] -> dst bf16 hi/lo [D][BT]
__global__ void actT_kernel(const float* __restrict__ src, bf16* __restrict__ dh,
                            bf16* __restrict__ dl) {
    __shared__ float t[32][33];
    int c0 = blockIdx.x * 32;
    int r0 = blockIdx.y * 32;
    int tx = threadIdx.x, ty = threadIdx.y;
#pragma unroll
    for (int kk = 0; kk < 4; kk++)
        t[ty + 8 * kk][tx] = src[(size_t)(r0 + ty + 8 * kk) * D + c0 + tx];
    __syncthreads();
#pragma unroll
    for (int kk = 0; kk < 4; kk++) {
        float v = t[tx][ty + 8 * kk];
        bf16 h, l;
        bsplit(v, h, l);
        size_t o = (size_t)(c0 + ty + 8 * kk) * BT + r0 + tx;
        dh[o] = h; dl[o] = l;
    }
}

// ---------------- elementwise / small kernels ----------------
__global__ void build_xm_kernel(const float* __restrict__ x, const float* __restrict__ meta) {
    size_t idx = (size_t)blockIdx.x * blockDim.x + threadIdx.x;
    if (idx >= BTD) return;
    int d = idx % D;
    int t = (idx / D) % T;
    int b = idx / ((size_t)D * T);
    float v = (t < M) ? meta[(size_t)t * D + d] : x[((size_t)b * S + (t - M)) * D + d];
    g_xm[idx] = v;
    bsplit(v, g_xm_h[idx], g_xm_l[idx]);
}

__global__ void wlr_kernel(const float* __restrict__ xm, const float* __restrict__ Wlr,
                           const float* __restrict__ blr, float* __restrict__ w) {
    int row = blockIdx.x * 8 + (threadIdx.x >> 5);
    int lane = threadIdx.x & 31;
    const float* xr = xm + (size_t)row * D;
    float s = 0.f;
    for (int d = lane; d < D; d += 32) s += xr[d] * Wlr[d];
#pragma unroll
    for (int off = 16; off > 0; off >>= 1) s += __shfl_xor_sync(0xffffffffu, s, off);
    if (lane == 0) {
        float z = s + blr[0];
        w[row] = (1.f / (1.f + __expf(-z))) * MAX_ALR;
    }
}

__device__ __forceinline__ float silu_grad(float z) {
    float sig = 1.f / (1.f + __expf(-z));
    return sig * (1.f + z * (1.f - sig));
}

__global__ void grad_out_kernel(const float* __restrict__ preds, const float* __restrict__ v,
                                const float* __restrict__ w, const float* __restrict__ z2) {
    size_t i = (size_t)blockIdx.x * blockDim.x + threadIdx.x;
    if (i >= BTD) return;
    int row = i / D;
    float g = w[row] * (2.0f / (float)D) * (preds[i] - v[i]);
    g_g2[i] = g;
    float d = g * silu_grad(z2[i]);
    g_dz2[i] = d;
    bsplit(d, g_dz2_h[i], g_dz2_l[i]);
}

__global__ void dz1_kernel(const float* __restrict__ g2, const float* __restrict__ dh1,
                           const float* __restrict__ z1) {
    size_t i = (size_t)blockIdx.x * blockDim.x + threadIdx.x;
    if (i >= BTD) return;
    g_dz1[i] = (g2[i] + dh1[i]) * silu_grad(z1[i]);
}

__global__ void colsum_kernel(const float* __restrict__ X, float* __restrict__ out, int rows) {
    int c = threadIdx.x;  // blockDim = 512 = D
    int r0 = blockIdx.x * 64;
    int r1 = min(r0 + 64, rows);
    float s = 0.f;
    for (int r = r0; r < r1; r++) s += X[(size_t)r * D + c];
    atomicAdd(&out[c], s);
}

__global__ void adamw_kernel(const float* __restrict__ p, const float* __restrict__ g,
                             float* __restrict__ out, int n) {
    int i = blockIdx.x * blockDim.x + threadIdx.x;
    if (i >= n) return;
    float gv = g[i];
    out[i] = p[i] * (1.f - LR * WD) - LR * gv / (fabsf(gv) + EPS);
}

// ---------------- sliding window attention (8 queries / block) ----------------
constexpr int QB = 8;
constexpr int KROWS = WIN + QB - 1;  // 135

__global__ __launch_bounds__(128) void attn_kernel2(const float* __restrict__ qkv) {
    __shared__ float Ksm[KROWS * 65];
    __shared__ float Qsm[QB * 64];
    __shared__ float sc[QB * 128];
    __shared__ float invs[QB];

    const float* qs = qkv;
    const float* ks = qkv + BTD;
    const float* vs = qkv + 2 * BTD;

    const int i0 = M + blockIdx.x * QB;
    const int h = blockIdx.y;
    const int b = blockIdx.z;
    const int tid = threadIdx.x;
    const int lane = tid & 31, w = tid >> 5;

    const int jlo = max(0, i0 - (WIN - 1));
    const int nrows = (i0 + QB - 1) - jlo + 1;

    for (int idx = tid; idx < nrows * 64; idx += 128) {
        int r = idx >> 6, d = idx & 63;
        Ksm[r * 65 + d] = ks[((size_t)(b * T + jlo + r)) * D + h * HD + d];
    }
    for (int idx = tid; idx < QB * 64; idx += 128)
        Qsm[idx] = qs[((size_t)(b * T + i0 + (idx >> 6))) * D + h * HD + (idx & 63)];
    __syncthreads();

#pragma unroll
    for (int q = 0; q < QB; q++) {
        int j = (i0 + q) - (WIN - 1) + tid;
        float s = -1e30f;
        if (j >= 0) {
            int r = j - jlo;
            const float* kp = &Ksm[r * 65];
            const float* qp = &Qsm[q * 64];
            float acc = 0.f;
#pragma unroll
            for (int d = 0; d < HD; d++) acc += qp[d] * kp[d];
            s = acc * 0.125f;
        }
        sc[q * 128 + tid] = s;
    }
    __syncthreads();

    for (int q = w; q < QB; q += 4) {
        float x0 = sc[q * 128 + lane];
        float x1 = sc[q * 128 + lane + 32];
        float x2 = sc[q * 128 + lane + 64];
        float x3 = sc[q * 128 + lane + 96];
        float mx = fmaxf(fmaxf(x0, x1), fmaxf(x2, x3));
#pragma unroll
        for (int off = 16; off > 0; off >>= 1) mx = fmaxf(mx, __shfl_xor_sync(0xffffffffu, mx, off));
        float e0 = __expf(x0 - mx), e1 = __expf(x1 - mx), e2 = __expf(x2 - mx), e3 = __expf(x3 - mx);
        sc[q * 128 + lane] = e0;
        sc[q * 128 + lane + 32] = e1;
        sc[q * 128 + lane + 64] = e2;
        sc[q * 128 + lane + 96] = e3;
        float sum = e0 + e1 + e2 + e3;
#pragma unroll
        for (int off = 16; off > 0; off >>= 1) sum += __shfl_xor_sync(0xffffffffu, sum, off);
        if (lane == 0) invs[q] = 1.f / sum;
    }
    __syncthreads();

    for (int idx = tid; idx < nrows * 64; idx += 128) {
        int r = idx >> 6, d = idx & 63;
        Ksm[r * 65 + d] = vs[((size_t)(b * T + jlo + r)) * D + h * HD + d];
    }
    __syncthreads();

    const int d = tid & 63, g = tid >> 6;
    float acc[4] = {0.f, 0.f, 0.f, 0.f};
    for (int r = 0; r < nrows; r++) {
        float vv = Ksm[r * 65 + d];
        int j = jlo + r;
#pragma unroll
        for (int qi = 0; qi < 4; qi++) {
            int q = g + qi * 2;
            int jj = j - (i0 + q) + (WIN - 1);
            if (jj >= 0 && jj < WIN) acc[qi] += sc[q * 128 + jj] * vv;
        }
    }
#pragma unroll
    for (int qi = 0; qi < 4; qi++) {
        int q = g + qi * 2;
        float ov = acc[qi] * invs[q];
        size_t off = ((size_t)(b * S + (i0 - M) + q)) * D + h * HD + d;
        bsplit(ov, g_o_h[off], g_o_l[off]);
    }
}

// ---------------- host-side launch ----------------
template <int EPI, int ZMODE>
static void launch_gemm(dim3 grid, const bf16* Ah, const bf16* Al, const bf16* Bh,
                        const bf16* Bl, const float* bias, const float* R, float* Cf,
                        bf16* Ch, bf16* Cl, float* Zf, int Md, int Nd, int Kd) {
    cudaFuncSetAttribute(gemm_bf16x3<EPI, ZMODE>,
                         cudaFuncAttributeMaxDynamicSharedMemorySize, GSMEM);
    gemm_bf16x3<EPI, ZMODE><<<grid, 512, GSMEM>>>(Ah, Al, Bh, Bl, bias, R, Cf, Ch, Cl, Zf,
                                                  Md, Nd, Kd);
}

template <typename Tsym>
static void* symp(Tsym& s) {
    void* p = nullptr;
    cudaGetSymbolAddress(&p, s);
    return p;
}

extern "C" void kernel_launch(void* const* d_in, const int* in_sizes, int n_in,
                              void* d_out, int out_size) {
    const float* x     = (const float*)d_in[0];
    const float* meta  = (const float*)d_in[1];
    const float* lmm_W = (const float*)d_in[2];
    const float* lmm_b = (const float*)d_in[3];
    const float* Wq    = (const float*)d_in[4];
    const float* bq    = (const float*)d_in[5];
    const float* Wk    = (const float*)d_in[6];
    const float* bk    = (const float*)d_in[7];
    const float* Wv    = (const float*)d_in[8];
    const float* bv    = (const float*)d_in[9];
    const float* W_lr  = (const float*)d_in[10];
    const float* b_lr  = (const float*)d_in[11];
    const float* swa_W = (const float*)d_in[12];
    const float* swa_b = (const float*)d_in[13];
    float* out = (float*)d_out;

    float *xm = (float*)symp(g_xm), *q = (float*)symp(g_q), *k = (float*)symp(g_k);
    float *v = (float*)symp(g_v), *w = (float*)symp(g_w);
    float *z1 = (float*)symp(g_z1), *h1 = (float*)symp(g_h1), *z2 = (float*)symp(g_z2);
    float *preds = (float*)symp(g_preds), *g2 = (float*)symp(g_g2);
    float *dz2 = (float*)symp(g_dz2), *dh1 = (float*)symp(g_dh1), *dz1 = (float*)symp(g_dz1);
    float *gW = (float*)symp(g_gW), *gb = (float*)symp(g_gb);
    float *Wu = (float*)symp(g_Wu), *bu = (float*)symp(g_bu);
    float *r1 = (float*)symp(g_r1), *qkv = (float*)symp(g_qkv), *part = (float*)symp(g_part);
    bf16 *xm_h = (bf16*)symp(g_xm_h), *xm_l = (bf16*)symp(g_xm_l);
    bf16 *q_h = (bf16*)symp(g_q_h), *q_l = (bf16*)symp(g_q_l);
    bf16 *k_h = (bf16*)symp(g_k_h), *k_l = (bf16*)symp(g_k_l);
    bf16 *h1_h = (bf16*)symp(g_h1_h), *h1_l = (bf16*)symp(g_h1_l);
    bf16 *dz2_h = (bf16*)symp(g_dz2_h), *dz2_l = (bf16*)symp(g_dz2_l);
    bf16 *r1_h = (bf16*)symp(g_r1_h), *r1_l = (bf16*)symp(g_r1_l);
    bf16 *r_h = (bf16*)symp(g_r_h), *r_l = (bf16*)symp(g_r_l);
    bf16 *o_h = (bf16*)symp(g_o_h), *o_l = (bf16*)symp(g_o_l);
    bf16 *kT_h = (bf16*)symp(g_kT_h), *kT_l = (bf16*)symp(g_kT_l);
    bf16 *h1T_h = (bf16*)symp(g_h1T_h), *h1T_l = (bf16*)symp(g_h1T_l);
    bf16 *dz2T_h = (bf16*)symp(g_dz2T_h), *dz2T_l = (bf16*)symp(g_dz2T_l);
    bf16 *dz1T_h = (bf16*)symp(g_dz1T_h), *dz1T_l = (bf16*)symp(g_dz1T_l);
    bf16 *wT_h = (bf16*)symp(g_wT_h), *wT_l = (bf16*)symp(g_wT_l);
    bf16 *w2o_h = (bf16*)symp(g_w2o_h), *w2o_l = (bf16*)symp(g_w2o_l);
    bf16 *wuT_h = (bf16*)symp(g_wuT_h), *wuT_l = (bf16*)symp(g_wuT_l);

    const int EW_BLK = 256;
    const int ew_grid = (int)((BTD + EW_BLK - 1) / EW_BLK);
    const dim3 gBT(D / 128, BT / 128);          // (4, 34)
    const dim3 gSWA(D / 128, BT / 128, 3);
    const dim3 gTN(D / 128, D / 128, SPLK);     // (4, 4, 8)
    const dim3 gOUT(D / 128, BS_ / 128);        // (4, 32)
    const dim3 tBlk(32, 8);
    const dim3 gActT(D / 32, BT / 32);

    // 0) weight splits (transposed; z=9 -> W2 original)
    wsplitT_kernel<<<dim3(16, 16, 10), tBlk>>>(Wq, Wk, Wv, lmm_W, lmm_W + DD, swa_W);

    // 1) xm = [meta ; x]
    build_xm_kernel<<<ew_grid, EW_BLK>>>(x, meta);

    // 2) projections
    launch_gemm<EPI_BIAS, 0>(gBT, xm_h, xm_l, wT_h + 0 * DD, wT_l + 0 * DD, bq, nullptr,
                             q, q_h, q_l, nullptr, BT, D, D);
    launch_gemm<EPI_BIAS, 0>(gBT, xm_h, xm_l, wT_h + 1 * DD, wT_l + 1 * DD, bk, nullptr,
                             k, k_h, k_l, nullptr, BT, D, D);
    launch_gemm<EPI_BIAS, 0>(gBT, xm_h, xm_l, wT_h + 2 * DD, wT_l + 2 * DD, bv, nullptr,
                             v, nullptr, nullptr, nullptr, BT, D, D);

    // 3) adaptive lr
    wlr_kernel<<<BT / 8, 256>>>(xm, W_lr, b_lr, w);

    // 4) lmm forward on k
    launch_gemm<EPI_RESSILU, 0>(gBT, k_h, k_l, wT_h + 3 * DD, wT_l + 3 * DD, lmm_b, k,
                                h1, h1_h, h1_l, z1, BT, D, D);
    launch_gemm<EPI_RESSILU, 0>(gBT, h1_h, h1_l, wT_h + 4 * DD, wT_l + 4 * DD, lmm_b + D, h1,
                                preds, nullptr, nullptr, z2, BT, D, D);

    // 5) backward
    grad_out_kernel<<<ew_grid, EW_BLK>>>(preds, v, w, z2);
    cudaMemsetAsync(gb, 0, 2 * D * sizeof(float));
    actT_kernel<<<gActT, tBlk>>>(k, kT_h, kT_l);
    actT_kernel<<<gActT, tBlk>>>(h1, h1T_h, h1T_l);
    actT_kernel<<<gActT, tBlk>>>(dz2, dz2T_h, dz2T_l);
    launch_gemm<EPI_NONE, 1>(gTN, h1T_h, h1T_l, dz2T_h, dz2T_l, nullptr, nullptr,
                             part, nullptr, nullptr, nullptr, D, D, BT);
    reduce_part_kernel<<<(DD + 255) / 256, 256>>>(part, gW + DD, DD);
    colsum_kernel<<<(BT + 63) / 64, D>>>(dz2, gb + D, BT);
    launch_gemm<EPI_NONE, 0>(gBT, dz2_h, dz2_l, w2o_h, w2o_l, nullptr, nullptr,
                             dh1, nullptr, nullptr, nullptr, BT, D, D);
    dz1_kernel<<<ew_grid, EW_BLK>>>(g2, dh1, z1);
    actT_kernel<<<gActT, tBlk>>>(dz1, dz1T_h, dz1T_l);
    launch_gemm<EPI_NONE, 1>(gTN, kT_h, kT_l, dz1T_h, dz1T_l, nullptr, nullptr,
                             part, nullptr, nullptr, nullptr, D, D, BT);
    reduce_part_kernel<<<(DD + 255) / 256, 256>>>(part, gW, DD);
    colsum_kernel<<<(BT + 63) / 64, D>>>(dz1, gb, BT);

    // 6) AdamW-style update + transpose-split of updated weights
    adamw_kernel<<<(2 * DD + 255) / 256, 256>>>(lmm_W, gW, Wu, 2 * DD);
    adamw_kernel<<<(2 * D + 255) / 256, 256>>>(lmm_b, gb, bu, 2 * D);
    wuT_kernel<<<dim3(16, 16, 2), tBlk>>>(Wu);

    // 7) retrieval with updated memory
    launch_gemm<EPI_RESSILU, 0>(gBT, q_h, q_l, wuT_h, wuT_l, bu, q,
                                r1, r1_h, r1_l, nullptr, BT, D, D);
    launch_gemm<EPI_RESSILU, 0>(gBT, r1_h, r1_l, wuT_h + DD, wuT_l + DD, bu + D, r1,
                                nullptr, r_h, r_l, nullptr, BT, D, D);

    // 8) SWA q/k/v projections (batched over z)
    launch_gemm<EPI_BIAS, 2>(gSWA, r_h, r_l, wT_h + 5 * DD, wT_l + 5 * DD, swa_b, nullptr,
                             qkv, nullptr, nullptr, nullptr, BT, D, D);

    // 9) attention -> compact bf16 o [B*S][D]
    {
        dim3 grid(S / QB, H, B);
        attn_kernel2<<<grid, 128>>>(qkv);
    }

    // 10) output projection -> d_out
    launch_gemm<EPI_BIAS, 0>(gOUT, o_h, o_l, wT_h + 8 * DD, wT_l + 8 * DD, swa_b + 3 * D,
                             nullptr, out, nullptr, nullptr, nullptr, BS_, D, D);
}

// round 7
// speedup vs baseline: 1.3152x; 1.0093x over previous
#include <cuda_runtime.h>
#include <cuda_bf16.h>
#include <math.h>
#include <stdint.h>

// ---------------- problem constants ----------------
constexpr int B = 4, S = 1024, D = 512, M = 64, H = 8, WIN = 128;
constexpr int T = M + S;            // 1088
constexpr int BT = B * T;           // 4352
constexpr int BS_ = B * S;          // 4096
constexpr int HD = D / H;           // 64
constexpr float LR = 1e-3f, WD = 1e-2f, MAX_ALR = 0.1f, EPS = 1e-8f;
constexpr size_t BTD = (size_t)BT * D;
constexpr size_t BSD = (size_t)BS_ * D;
constexpr int DD = D * D;
constexpr int SPLK = 8;             // 4352/8 = 544 = 17*32

typedef __nv_bfloat16 bf16;

// ---------------- scratch (static device globals; no allocation) ----------------
__device__ float g_xm[BTD];
__device__ float g_q[BTD];
__device__ float g_k[BTD];
__device__ float g_v[BTD];
__device__ float g_w[BT];
__device__ float g_z1[BTD];
__device__ float g_h1[BTD];
__device__ float g_z2[BTD];
__device__ float g_preds[BTD];
__device__ float g_g2[BTD];
__device__ float g_dz2[BTD];
__device__ float g_dh1[BTD];
__device__ float g_dz1[BTD];
__device__ float g_gW[2 * DD];
__device__ float g_gb[2 * D];
__device__ float g_Wu[2 * DD];
__device__ float g_bu[2 * D];
__device__ float g_r1[BTD];
__device__ float g_qkv[3 * BTD];
__device__ float g_part[SPLK * DD];
// bf16 hi/lo activations (row-major [rows][k])
__device__ bf16 g_xm_h[BTD], g_xm_l[BTD];
__device__ bf16 g_q_h[BTD], g_q_l[BTD];
__device__ bf16 g_k_h[BTD], g_k_l[BTD];
__device__ bf16 g_h1_h[BTD], g_h1_l[BTD];
__device__ bf16 g_dz2_h[BTD], g_dz2_l[BTD];
__device__ bf16 g_r1_h[BTD], g_r1_l[BTD];
__device__ bf16 g_r_h[BTD], g_r_l[BTD];
__device__ bf16 g_o_h[BSD], g_o_l[BSD];
// bf16 transposed activations [D][BT]
__device__ bf16 g_kT_h[BTD], g_kT_l[BTD];
__device__ bf16 g_h1T_h[BTD], g_h1T_l[BTD];
__device__ bf16 g_dz2T_h[BTD], g_dz2T_l[BTD];
__device__ bf16 g_dz1T_h[BTD], g_dz1T_l[BTD];
// bf16 weights: transposed [out][in] slots 0..8 = Wq,Wk,Wv,W1,W2,swa0..3
__device__ bf16 g_wT_h[9 * DD], g_wT_l[9 * DD];
__device__ bf16 g_w2o_h[DD], g_w2o_l[DD];
__device__ bf16 g_wuT_h[2 * DD], g_wuT_l[2 * DD];

// ---------------- helpers ----------------
__device__ __forceinline__ void bsplit(float f, bf16& h, bf16& l) {
    h = __float2bfloat16(f);
    l = __float2bfloat16(f - __bfloat162float(h));
}

__device__ __forceinline__ void mma_bf16(float* d, const uint32_t* a, const uint32_t* b) {
    asm volatile(
        "mma.sync.aligned.m16n8k16.row.col.f32.bf16.bf16.f32 "
        "{%0,%1,%2,%3}, {%4,%5,%6,%7}, {%8,%9}, {%0,%1,%2,%3};"
        : "+f"(d[0]), "+f"(d[1]), "+f"(d[2]), "+f"(d[3])
        : "r"(a[0]), "r"(a[1]), "r"(a[2]), "r"(a[3]), "r"(b[0]), "r"(b[1]));
}

__device__ __forceinline__ void ldsm_x4(uint32_t& r0, uint32_t& r1, uint32_t& r2,
                                        uint32_t& r3, uint32_t addr) {
    asm volatile("ldmatrix.sync.aligned.m8n8.x4.shared.b16 {%0,%1,%2,%3}, [%4];"
                 : "=r"(r0), "=r"(r1), "=r"(r2), "=r"(r3) : "r"(addr));
}

__device__ __forceinline__ void cp_async16(uint32_t sa, const void* gptr) {
    asm volatile("cp.async.cg.shared.global [%0], [%1], 16;" :: "r"(sa), "l"(gptr));
}
__device__ __forceinline__ void cp_commit() { asm volatile("cp.async.commit_group;"); }
template <int N>
__device__ __forceinline__ void cp_wait() { asm volatile("cp.async.wait_group %0;" :: "n"(N)); }

// ---------------- bf16x3 GEMM, 512 threads, ldmatrix fragments ----------------
// C[m,n] = sum_k A[m][k]*B[n][k], A/B pre-split bf16 hi/lo, 128x128 tile, BK=32.
#define EPI_BIAS 0
#define EPI_NONE 1
#define EPI_RESSILU 2

constexpr int ROWB = 80;                      // 64B data + 16B pad -> conflict-free LDSM
constexpr int TILE_B = 128 * ROWB;            // 10240 B per half-tile
constexpr int STAGE_B = 4 * TILE_B;           // Ahi,Alo,Bhi,Blo = 40960 B
constexpr int NSTG = 3;
constexpr int GSMEM = NSTG * STAGE_B;         // 122880 B

template <int EPI, int ZMODE>  // ZMODE: 0 none; 1 split-K z; 2 batched weights z
__global__ __launch_bounds__(512, 1) void gemm_bf16x3(
    const bf16* __restrict__ Ah, const bf16* __restrict__ Al,
    const bf16* __restrict__ Bh, const bf16* __restrict__ Bl,
    const float* __restrict__ bias, const float* __restrict__ R,
    float* __restrict__ Cf, bf16* __restrict__ Ch, bf16* __restrict__ Cl,
    float* __restrict__ Zf, int Md, int Nd, int Kd) {
    extern __shared__ char smem[];
    const uint32_t sbase = (uint32_t)__cvta_generic_to_shared(smem);

    const int n0 = blockIdx.x * 128;
    const int m0 = blockIdx.y * 128;
    const int tid = threadIdx.x;
    const int warp = tid >> 5, lane = tid & 31;
    const int wm = warp >> 2, wn = warp & 3;    // 4 x 4 warp grid, 32x32 warp tile
    const int gid = lane >> 2, tig = lane & 3;

    if (ZMODE == 2) {
        size_t wo = (size_t)blockIdx.z * Kd * Nd;
        Bh += wo; Bl += wo;
        bias += (size_t)blockIdx.z * Nd;
        Cf += (size_t)blockIdx.z * Md * Nd;
    }
    int kbeg = 0, kend = Kd;
    if (ZMODE == 1) {
        int chunk = Kd / SPLK;
        kbeg = blockIdx.z * chunk;
        kend = kbeg + chunk;
        Cf += (size_t)blockIdx.z * Md * Nd;
    }
    const int nIter = (kend - kbeg) / 32;

    float acc[2][4][4];
#pragma unroll
    for (int i = 0; i < 2; i++)
#pragma unroll
        for (int j = 0; j < 4; j++)
#pragma unroll
            for (int c = 0; c < 4; c++) acc[i][j][c] = 0.f;

    // ---- LDSM address terms (per-thread, loop-invariant) ----
    // A x4 (per im): matrices m0k0, m8k0, m0k8, m8k8
    uint32_t aterm[2], bterm[2];
#pragma unroll
    for (int im = 0; im < 2; im++)
        aterm[im] = (uint32_t)((wm * 32 + im * 16 + ((lane >> 3) & 1) * 8 + (lane & 7)) * ROWB
                               + ((lane >> 4) & 1) * 16);
    // B x4 (per jn-pair p): matrices b0(jn),b1(jn),b0(jn+1),b1(jn+1)
#pragma unroll
    for (int p = 0; p < 2; p++)
        bterm[p] = (uint32_t)((wn * 32 + p * 16 + ((lane >> 4) & 1) * 8 + (lane & 7)) * ROWB
                               + ((lane >> 3) & 1) * 16);

    // loader: 512 threads, one 16B chunk per half-tile per thread
    const int lrow = tid >> 2, lc = tid & 3;
    auto loadStage = [&](int k0, int st) {
        uint32_t d0 = sbase + st * STAGE_B + lrow * ROWB + lc * 16;
        const size_t ga = (size_t)(m0 + lrow) * Kd + k0 + lc * 8;
        const size_t gb = (size_t)(n0 + lrow) * Kd + k0 + lc * 8;
        cp_async16(d0, Ah + ga);
        cp_async16(d0 + TILE_B, Al + ga);
        cp_async16(d0 + 2 * TILE_B, Bh + gb);
        cp_async16(d0 + 3 * TILE_B, Bl + gb);
        cp_commit();
    };

    loadStage(kbeg, 0);
    loadStage(kbeg + 32, 1);
    loadStage(kbeg + 64, 2);

    for (int it = 0; it < nIter; it++) {
        int rem = nIter - 1 - it;
        if (rem >= 2) cp_wait<2>();
        else if (rem == 1) cp_wait<1>();
        else cp_wait<0>();
        __syncthreads();

        const uint32_t so = sbase + (it % NSTG) * STAGE_B;

#pragma unroll
        for (int s = 0; s < 2; s++) {
            const uint32_t ks = s * 32;  // chunk advance: k16 = 2 chunks of 16B
            uint32_t ah[2][4], al[2][4];
#pragma unroll
            for (int im = 0; im < 2; im++) {
                ldsm_x4(ah[im][0], ah[im][1], ah[im][2], ah[im][3], so + aterm[im] + ks);
                ldsm_x4(al[im][0], al[im][1], al[im][2], al[im][3],
                        so + TILE_B + aterm[im] + ks);
            }
            uint32_t bh[4][2], bl[4][2];
#pragma unroll
            for (int p = 0; p < 2; p++) {
                ldsm_x4(bh[2 * p][0], bh[2 * p][1], bh[2 * p + 1][0], bh[2 * p + 1][1],
                        so + 2 * TILE_B + bterm[p] + ks);
                ldsm_x4(bl[2 * p][0], bl[2 * p][1], bl[2 * p + 1][0], bl[2 * p + 1][1],
                        so + 3 * TILE_B + bterm[p] + ks);
            }
#pragma unroll
            for (int im = 0; im < 2; im++)
#pragma unroll
                for (int jn = 0; jn < 4; jn++) {
                    mma_bf16(acc[im][jn], ah[im], bh[jn]);
                    mma_bf16(acc[im][jn], ah[im], bl[jn]);
                    mma_bf16(acc[im][jn], al[im], bh[jn]);
                }
        }
        __syncthreads();

        if (it + NSTG < nIter)
            loadStage(kbeg + (it + NSTG) * 32, (it + NSTG) % NSTG);
    }

    // ---- epilogue ----
#pragma unroll
    for (int im = 0; im < 2; im++) {
#pragma unroll
        for (int jn = 0; jn < 4; jn++) {
            int col = n0 + wn * 32 + jn * 8 + tig * 2;
#pragma unroll
            for (int rr = 0; rr < 2; rr++) {
                int r_ = m0 + wm * 32 + im * 16 + gid + rr * 8;
                float v0 = acc[im][jn][rr * 2 + 0];
                float v1 = acc[im][jn][rr * 2 + 1];
                if (EPI == EPI_BIAS || EPI == EPI_RESSILU) {
                    v0 += bias[col];
                    v1 += bias[col + 1];
                }
                size_t off = (size_t)r_ * Nd + col;
                if (EPI == EPI_RESSILU) {
                    if (Zf) { Zf[off] = v0; Zf[off + 1] = v1; }
                    float s0 = 1.f / (1.f + __expf(-v0));
                    float s1 = 1.f / (1.f + __expf(-v1));
                    v0 = R[off] + v0 * s0;
                    v1 = R[off + 1] + v1 * s1;
                }
                if (Cf) { Cf[off] = v0; Cf[off + 1] = v1; }
                if (Ch) {
                    bf16 h0, l0, h1, l1;
                    bsplit(v0, h0, l0);
                    bsplit(v1, h1, l1);
                    Ch[off] = h0; Ch[off + 1] = h1;
                    Cl[off] = l0; Cl[off + 1] = l1;
                }
            }
        }
    }
}

// ---------------- split-K reduce ----------------
__global__ void reduce_part_kernel(const float* __restrict__ part, float* __restrict__ out, int n) {
    int i = blockIdx.x * 256 + threadIdx.x;
    if (i >= n) return;
    float s = 0.f;
#pragma unroll
    for (int z = 0; z < SPLK; z++) s += part[(size_t)z * n + i];
    out[i] = s;
}

// ---------------- weight split (transposed + W2 original), z = 0..9 ----------------
__global__ void wsplitT_kernel(const float* __restrict__ Wq, const float* __restrict__ Wk,
                               const float* __restrict__ Wv, const float* __restrict__ W1,
                               const float* __restrict__ W2, const float* __restrict__ swa) {
    __shared__ float t[32][33];
    int z = blockIdx.z;
    const float* src = (z == 0) ? Wq : (z == 1) ? Wk : (z == 2) ? Wv : (z == 3) ? W1
                     : (z == 4 || z == 9) ? W2 : swa + (size_t)(z - 5) * DD;
    int c0 = blockIdx.x * 32, r0 = blockIdx.y * 32;
    int tx = threadIdx.x, ty = threadIdx.y;  // (32, 8)
#pragma unroll
    for (int kk = 0; kk < 4; kk++)
        t[ty + 8 * kk][tx] = src[(size_t)(r0 + ty + 8 * kk) * D + c0 + tx];
    __syncthreads();
    if (z < 9) {
        bf16* dh = g_wT_h + (size_t)z * DD;
        bf16* dl = g_wT_l + (size_t)z * DD;
#pragma unroll
        for (int kk = 0; kk < 4; kk++) {
            float v = t[tx][ty + 8 * kk];
            bf16 h, l;
            bsplit(v, h, l);
            size_t o = (size_t)(c0 + ty + 8 * kk) * D + r0 + tx;
            dh[o] = h; dl[o] = l;
        }
    } else {
#pragma unroll
        for (int kk = 0; kk < 4; kk++) {
            float v = t[ty + 8 * kk][tx];
            bf16 h, l;
            bsplit(v, h, l);
            size_t o = (size_t)(r0 + ty + 8 * kk) * D + c0 + tx;
            g_w2o_h[o] = h; g_w2o_l[o] = l;
        }
    }
}

__global__ void wuT_kernel(const float* __restrict__ Wu) {
    __shared__ float t[32][33];
    int z = blockIdx.z;
    const float* src = Wu + (size_t)z * DD;
    bf16* dh = g_wuT_h + (size_t)z * DD;
    bf16* dl = g_wuT_l + (size_t)z * DD;
    int c0 = blockIdx.x * 32, r0 = blockIdx.y * 32;
    int tx = threadIdx.x, ty = threadIdx.y;
#pragma unroll
    for (int kk = 0; kk < 4; kk++)
        t[ty + 8 * kk][tx] = src[(size_t)(r0 + ty + 8 * kk) * D + c0 + tx];
    __syncthreads();
#pragma unroll
    for (int kk = 0; kk < 4; kk++) {
        float v = t[tx][ty + 8 * kk];
        bf16 h, l;
        bsplit(v, h, l);
        size_t o = (size_t)(c0 + ty + 8 * kk) * D + r0 + tx;
        dh[o] = h; dl[o] = l;
    }
}

// activation transpose-split: src f32 [BT][D] -> dst bf16 hi/lo [D][BT]
__global__ void actT_kernel(const float* __restrict__ src, bf16* __restrict__ dh,
                            bf16* __restrict__ dl) {
    __shared__ float t[32][33];
    int c0 = blockIdx.x * 32;
    int r0 = blockIdx.y * 32;
    int tx = threadIdx.x, ty = threadIdx.y;
#pragma unroll
    for (int kk = 0; kk < 4; kk++)
        t[ty + 8 * kk][tx] = src[(size_t)(r0 + ty + 8 * kk) * D + c0 + tx];
    __syncthreads();
#pragma unroll
    for (int kk = 0; kk < 4; kk++) {
        float v = t[tx][ty + 8 * kk];
        bf16 h, l;
        bsplit(v, h, l);
        size_t o = (size_t)(c0 + ty + 8 * kk) * BT + r0 + tx;
        dh[o] = h; dl[o] = l;
    }
}

// ---------------- elementwise / small kernels ----------------
__global__ void build_xm_kernel(const float* __restrict__ x, const float* __restrict__ meta) {
    size_t idx = (size_t)blockIdx.x * blockDim.x + threadIdx.x;
    if (idx >= BTD) return;
    int d = idx % D;
    int t = (idx / D) % T;
    int b = idx / ((size_t)D * T);
    float v = (t < M) ? meta[(size_t)t * D + d] : x[((size_t)b * S + (t - M)) * D + d];
    g_xm[idx] = v;
    bsplit(v, g_xm_h[idx], g_xm_l[idx]);
}

__global__ void wlr_kernel(const float* __restrict__ xm, const float* __restrict__ Wlr,
                           const float* __restrict__ blr, float* __restrict__ w) {
    int row = blockIdx.x * 8 + (threadIdx.x >> 5);
    int lane = threadIdx.x & 31;
    const float* xr = xm + (size_t)row * D;
    float s = 0.f;
    for (int d = lane; d < D; d += 32) s += xr[d] * Wlr[d];
#pragma unroll
    for (int off = 16; off > 0; off >>= 1) s += __shfl_xor_sync(0xffffffffu, s, off);
    if (lane == 0) {
        float z = s + blr[0];
        w[row] = (1.f / (1.f + __expf(-z))) * MAX_ALR;
    }
}

__device__ __forceinline__ float silu_grad(float z) {
    float sig = 1.f / (1.f + __expf(-z));
    return sig * (1.f + z * (1.f - sig));
}

__global__ void grad_out_kernel(const float* __restrict__ preds, const float* __restrict__ v,
                                const float* __restrict__ w, const float* __restrict__ z2) {
    size_t i = (size_t)blockIdx.x * blockDim.x + threadIdx.x;
    if (i >= BTD) return;
    int row = i / D;
    float g = w[row] * (2.0f / (float)D) * (preds[i] - v[i]);
    g_g2[i] = g;
    float d = g * silu_grad(z2[i]);
    g_dz2[i] = d;
    bsplit(d, g_dz2_h[i], g_dz2_l[i]);
}

__global__ void dz1_kernel(const float* __restrict__ g2, const float* __restrict__ dh1,
                           const float* __restrict__ z1) {
    size_t i = (size_t)blockIdx.x * blockDim.x + threadIdx.x;
    if (i >= BTD) return;
    g_dz1[i] = (g2[i] + dh1[i]) * silu_grad(z1[i]);
}

__global__ void colsum_kernel(const float* __restrict__ X, float* __restrict__ out, int rows) {
    int c = threadIdx.x;  // blockDim = 512 = D
    int r0 = blockIdx.x * 64;
    int r1 = min(r0 + 64, rows);
    float s = 0.f;
    for (int r = r0; r < r1; r++) s += X[(size_t)r * D + c];
    atomicAdd(&out[c], s);
}

__global__ void adamw_kernel(const float* __restrict__ p, const float* __restrict__ g,
                             float* __restrict__ out, int n) {
    int i = blockIdx.x * blockDim.x + threadIdx.x;
    if (i >= n) return;
    float gv = g[i];
    out[i] = p[i] * (1.f - LR * WD) - LR * gv / (fabsf(gv) + EPS);
}

// ---------------- sliding window attention (8 queries / block) ----------------
constexpr int QB = 8;
constexpr int KROWS = WIN + QB - 1;  // 135

__global__ __launch_bounds__(128) void attn_kernel2(const float* __restrict__ qkv) {
    __shared__ float Ksm[KROWS * 65];
    __shared__ float Qsm[QB * 64];
    __shared__ float sc[QB * 128];
    __shared__ float invs[QB];

    const float* qs = qkv;
    const float* ks = qkv + BTD;
    const float* vs = qkv + 2 * BTD;

    const int i0 = M + blockIdx.x * QB;
    const int h = blockIdx.y;
    const int b = blockIdx.z;
    const int tid = threadIdx.x;
    const int lane = tid & 31, w = tid >> 5;

    const int jlo = max(0, i0 - (WIN - 1));
    const int nrows = (i0 + QB - 1) - jlo + 1;

    for (int idx = tid; idx < nrows * 64; idx += 128) {
        int r = idx >> 6, d = idx & 63;
        Ksm[r * 65 + d] = ks[((size_t)(b * T + jlo + r)) * D + h * HD + d];
    }
    for (int idx = tid; idx < QB * 64; idx += 128)
        Qsm[idx] = qs[((size_t)(b * T + i0 + (idx >> 6))) * D + h * HD + (idx & 63)];
    __syncthreads();

#pragma unroll
    for (int q = 0; q < QB; q++) {
        int j = (i0 + q) - (WIN - 1) + tid;
        float s = -1e30f;
        if (j >= 0) {
            int r = j - jlo;
            const float* kp = &Ksm[r * 65];
            const float* qp = &Qsm[q * 64];
            float acc = 0.f;
#pragma unroll
            for (int d = 0; d < HD; d++) acc += qp[d] * kp[d];
            s = acc * 0.125f;
        }
        sc[q * 128 + tid] = s;
    }
    __syncthreads();

    for (int q = w; q < QB; q += 4) {
        float x0 = sc[q * 128 + lane];
        float x1 = sc[q * 128 + lane + 32];
        float x2 = sc[q * 128 + lane + 64];
        float x3 = sc[q * 128 + lane + 96];
        float mx = fmaxf(fmaxf(x0, x1), fmaxf(x2, x3));
#pragma unroll
        for (int off = 16; off > 0; off >>= 1) mx = fmaxf(mx, __shfl_xor_sync(0xffffffffu, mx, off));
        float e0 = __expf(x0 - mx), e1 = __expf(x1 - mx), e2 = __expf(x2 - mx), e3 = __expf(x3 - mx);
        sc[q * 128 + lane] = e0;
        sc[q * 128 + lane + 32] = e1;
        sc[q * 128 + lane + 64] = e2;
        sc[q * 128 + lane + 96] = e3;
        float sum = e0 + e1 + e2 + e3;
#pragma unroll
        for (int off = 16; off > 0; off >>= 1) sum += __shfl_xor_sync(0xffffffffu, sum, off);
        if (lane == 0) invs[q] = 1.f / sum;
    }
    __syncthreads();

    for (int idx = tid; idx < nrows * 64; idx += 128) {
        int r = idx >> 6, d = idx & 63;
        Ksm[r * 65 + d] = vs[((size_t)(b * T + jlo + r)) * D + h * HD + d];
    }
    __syncthreads();

    const int d = tid & 63, g = tid >> 6;
    float acc[4] = {0.f, 0.f, 0.f, 0.f};
    for (int r = 0; r < nrows; r++) {
        float vv = Ksm[r * 65 + d];
        int j = jlo + r;
#pragma unroll
        for (int qi = 0; qi < 4; qi++) {
            int q = g + qi * 2;
            int jj = j - (i0 + q) + (WIN - 1);
            if (jj >= 0 && jj < WIN) acc[qi] += sc[q * 128 + jj] * vv;
        }
    }
#pragma unroll
    for (int qi = 0; qi < 4; qi++) {
        int q = g + qi * 2;
        float ov = acc[qi] * invs[q];
        size_t off = ((size_t)(b * S + (i0 - M) + q)) * D + h * HD + d;
        bsplit(ov, g_o_h[off], g_o_l[off]);
    }
}

// ---------------- host-side launch ----------------
template <int EPI, int ZMODE>
static void launch_gemm(dim3 grid, const bf16* Ah, const bf16* Al, const bf16* Bh,
                        const bf16* Bl, const float* bias, const float* R, float* Cf,
                        bf16* Ch, bf16* Cl, float* Zf, int Md, int Nd, int Kd) {
    cudaFuncSetAttribute(gemm_bf16x3<EPI, ZMODE>,
                         cudaFuncAttributeMaxDynamicSharedMemorySize, GSMEM);
    gemm_bf16x3<EPI, ZMODE><<<grid, 512, GSMEM>>>(Ah, Al, Bh, Bl, bias, R, Cf, Ch, Cl, Zf,
                                                  Md, Nd, Kd);
}

template <typename Tsym>
static void* symp(Tsym& s) {
    void* p = nullptr;
    cudaGetSymbolAddress(&p, s);
    return p;
}

extern "C" void kernel_launch(void* const* d_in, const int* in_sizes, int n_in,
                              void* d_out, int out_size) {
    const float* x     = (const float*)d_in[0];
    const float* meta  = (const float*)d_in[1];
    const float* lmm_W = (const float*)d_in[2];
    const float* lmm_b = (const float*)d_in[3];
    const float* Wq    = (const float*)d_in[4];
    const float* bq    = (const float*)d_in[5];
    const float* Wk    = (const float*)d_in[6];
    const float* bk    = (const float*)d_in[7];
    const float* Wv    = (const float*)d_in[8];
    const float* bv    = (const float*)d_in[9];
    const float* W_lr  = (const float*)d_in[10];
    const float* b_lr  = (const float*)d_in[11];
    const float* swa_W = (const float*)d_in[12];
    const float* swa_b = (const float*)d_in[13];
    float* out = (float*)d_out;

    float *xm = (float*)symp(g_xm), *q = (float*)symp(g_q), *k = (float*)symp(g_k);
    float *v = (float*)symp(g_v), *w = (float*)symp(g_w);
    float *z1 = (float*)symp(g_z1), *h1 = (float*)symp(g_h1), *z2 = (float*)symp(g_z2);
    float *preds = (float*)symp(g_preds), *g2 = (float*)symp(g_g2);
    float *dz2 = (float*)symp(g_dz2), *dh1 = (float*)symp(g_dh1), *dz1 = (float*)symp(g_dz1);
    float *gW = (float*)symp(g_gW), *gb = (float*)symp(g_gb);
    float *Wu = (float*)symp(g_Wu), *bu = (float*)symp(g_bu);
    float *r1 = (float*)symp(g_r1), *qkv = (float*)symp(g_qkv), *part = (float*)symp(g_part);
    bf16 *xm_h = (bf16*)symp(g_xm_h), *xm_l = (bf16*)symp(g_xm_l);
    bf16 *q_h = (bf16*)symp(g_q_h), *q_l = (bf16*)symp(g_q_l);
    bf16 *k_h = (bf16*)symp(g_k_h), *k_l = (bf16*)symp(g_k_l);
    bf16 *h1_h = (bf16*)symp(g_h1_h), *h1_l = (bf16*)symp(g_h1_l);
    bf16 *dz2_h = (bf16*)symp(g_dz2_h), *dz2_l = (bf16*)symp(g_dz2_l);
    bf16 *r1_h = (bf16*)symp(g_r1_h), *r1_l = (bf16*)symp(g_r1_l);
    bf16 *r_h = (bf16*)symp(g_r_h), *r_l = (bf16*)symp(g_r_l);
    bf16 *o_h = (bf16*)symp(g_o_h), *o_l = (bf16*)symp(g_o_l);
    bf16 *kT_h = (bf16*)symp(g_kT_h), *kT_l = (bf16*)symp(g_kT_l);
    bf16 *h1T_h = (bf16*)symp(g_h1T_h), *h1T_l = (bf16*)symp(g_h1T_l);
    bf16 *dz2T_h = (bf16*)symp(g_dz2T_h), *dz2T_l = (bf16*)symp(g_dz2T_l);
    bf16 *dz1T_h = (bf16*)symp(g_dz1T_h), *dz1T_l = (bf16*)symp(g_dz1T_l);
    bf16 *wT_h = (bf16*)symp(g_wT_h), *wT_l = (bf16*)symp(g_wT_l);
    bf16 *w2o_h = (bf16*)symp(g_w2o_h), *w2o_l = (bf16*)symp(g_w2o_l);
    bf16 *wuT_h = (bf16*)symp(g_wuT_h), *wuT_l = (bf16*)symp(g_wuT_l);

    const int EW_BLK = 256;
    const int ew_grid = (int)((BTD + EW_BLK - 1) / EW_BLK);
    const dim3 gBT(D / 128, BT / 128);          // (4, 34)
    const dim3 gSWA(D / 128, BT / 128, 3);
    const dim3 gTN(D / 128, D / 128, SPLK);     // (4, 4, 8)
    const dim3 gOUT(D / 128, BS_ / 128);        // (4, 32)
    const dim3 tBlk(32, 8);
    const dim3 gActT(D / 32, BT / 32);

    // 0) weight splits (transposed; z=9 -> W2 original)
    wsplitT_kernel<<<dim3(16, 16, 10), tBlk>>>(Wq, Wk, Wv, lmm_W, lmm_W + DD, swa_W);

    // 1) xm = [meta ; x]
    build_xm_kernel<<<ew_grid, EW_BLK>>>(x, meta);

    // 2) projections
    launch_gemm<EPI_BIAS, 0>(gBT, xm_h, xm_l, wT_h + 0 * DD, wT_l + 0 * DD, bq, nullptr,
                             q, q_h, q_l, nullptr, BT, D, D);
    launch_gemm<EPI_BIAS, 0>(gBT, xm_h, xm_l, wT_h + 1 * DD, wT_l + 1 * DD, bk, nullptr,
                             k, k_h, k_l, nullptr, BT, D, D);
    launch_gemm<EPI_BIAS, 0>(gBT, xm_h, xm_l, wT_h + 2 * DD, wT_l + 2 * DD, bv, nullptr,
                             v, nullptr, nullptr, nullptr, BT, D, D);

    // 3) adaptive lr
    wlr_kernel<<<BT / 8, 256>>>(xm, W_lr, b_lr, w);

    // 4) lmm forward on k
    launch_gemm<EPI_RESSILU, 0>(gBT, k_h, k_l, wT_h + 3 * DD, wT_l + 3 * DD, lmm_b, k,
                                h1, h1_h, h1_l, z1, BT, D, D);
    launch_gemm<EPI_RESSILU, 0>(gBT, h1_h, h1_l, wT_h + 4 * DD, wT_l + 4 * DD, lmm_b + D, h1,
                                preds, nullptr, nullptr, z2, BT, D, D);

    // 5) backward
    grad_out_kernel<<<ew_grid, EW_BLK>>>(preds, v, w, z2);
    cudaMemsetAsync(gb, 0, 2 * D * sizeof(float));
    actT_kernel<<<gActT, tBlk>>>(k, kT_h, kT_l);
    actT_kernel<<<gActT, tBlk>>>(h1, h1T_h, h1T_l);
    actT_kernel<<<gActT, tBlk>>>(dz2, dz2T_h, dz2T_l);
    launch_gemm<EPI_NONE, 1>(gTN, h1T_h, h1T_l, dz2T_h, dz2T_l, nullptr, nullptr,
                             part, nullptr, nullptr, nullptr, D, D, BT);
    reduce_part_kernel<<<(DD + 255) / 256, 256>>>(part, gW + DD, DD);
    colsum_kernel<<<(BT + 63) / 64, D>>>(dz2, gb + D, BT);
    launch_gemm<EPI_NONE, 0>(gBT, dz2_h, dz2_l, w2o_h, w2o_l, nullptr, nullptr,
                             dh1, nullptr, nullptr, nullptr, BT, D, D);
    dz1_kernel<<<ew_grid, EW_BLK>>>(g2, dh1, z1);
    actT_kernel<<<gActT, tBlk>>>(dz1, dz1T_h, dz1T_l);
    launch_gemm<EPI_NONE, 1>(gTN, kT_h, kT_l, dz1T_h, dz1T_l, nullptr, nullptr,
                             part, nullptr, nullptr, nullptr, D, D, BT);
    reduce_part_kernel<<<(DD + 255) / 256, 256>>>(part, gW, DD);
    colsum_kernel<<<(BT + 63) / 64, D>>>(dz1, gb, BT);

    // 6) AdamW-style update + transpose-split of updated weights
    adamw_kernel<<<(2 * DD + 255) / 256, 256>>>(lmm_W, gW, Wu, 2 * DD);
    adamw_kernel<<<(2 * D + 255) / 256, 256>>>(lmm_b, gb, bu, 2 * D);
    wuT_kernel<<<dim3(16, 16, 2), tBlk>>>(Wu);

    // 7) retrieval with updated memory
    launch_gemm<EPI_RESSILU, 0>(gBT, q_h, q_l, wuT_h, wuT_l, bu, q,
                                r1, r1_h, r1_l, nullptr, BT, D, D);
    launch_gemm<EPI_RESSILU, 0>(gBT, r1_h, r1_l, wuT_h + DD, wuT_l + DD, bu + D, r1,
                                nullptr, r_h, r_l, nullptr, BT, D, D);

    // 8) SWA q/k/v projections (batched over z)
    launch_gemm<EPI_BIAS, 2>(gSWA, r_h, r_l, wT_h + 5 * DD, wT_l + 5 * DD, swa_b, nullptr,
                             qkv, nullptr, nullptr, nullptr, BT, D, D);

    // 9) attention -> compact bf16 o [B*S][D]
    {
        dim3 grid(S / QB, H, B);
        attn_kernel2<<<grid, 128>>>(qkv);
    }

    // 10) output projection -> d_out
    launch_gemm<EPI_BIAS, 0>(gOUT, o_h, o_l, wT_h + 8 * DD, wT_l + 8 * DD, swa_b + 3 * D,
                             nullptr, out, nullptr, nullptr, nullptr, BS_, D, D);
}